// round 1
// baseline (speedup 1.0000x reference)
#include <cuda_runtime.h>
#include <cuda_bf16.h>
#include <math.h>

// Problem constants
#define T_TOK 2048
#define HID   4096
#define NH    32
#define NKV   8
#define HD    128
#define QKV_W ((NH + 2*NKV) * HD)   // 6144
#define OUT_W (NH * HD)             // 4096

// Scratch (allocation-free requirement -> device globals)
__device__ float g_qkv[(size_t)T_TOK * QKV_W];     // 50.3 MB
__device__ float g_attn[(size_t)T_TOK * OUT_W];    // 33.6 MB
__device__ float g_invfreq_pi[HD/2];

// ---------------------------------------------------------------------------
// inv_freq table (divided by pi, so we can use cospif/sinpif which are NOT
// remapped by --use_fast_math and do exact range reduction)
// ---------------------------------------------------------------------------
__global__ void init_invfreq_kernel() {
    int i = threadIdx.x;  // 0..63
    double inv = pow(1.0e6, -((double)(2 * i)) / 128.0);
    g_invfreq_pi[i] = (float)(inv / 3.14159265358979323846);
}

// ---------------------------------------------------------------------------
// GPT-J interleaved RoPE, applied in-place to q heads (0..31) and k heads
// (32..39) of the qkv buffer (q cols [0,4096), k cols [4096,5120) -> heads
// 0..39 are contiguous at h*128).
// ---------------------------------------------------------------------------
__global__ void rope_kernel(const int* __restrict__ positions,
                            float* __restrict__ qkv) {
    int t = blockIdx.x;
    int h = blockIdx.y;        // 0..39
    int i = threadIdx.x;       // 0..63
    float pos = (float)positions[t];
    float f = pos * g_invfreq_pi[i];
    float c = cospif(f);
    float s = sinpif(f);
    float* base = qkv + (size_t)t * QKV_W + h * HD;
    float x1 = base[2 * i];
    float x2 = base[2 * i + 1];
    base[2 * i]     = x1 * c - x2 * s;
    base[2 * i + 1] = x2 * c + x1 * s;
}

// ---------------------------------------------------------------------------
// SGEMM: C[M,N] = A[M,K] @ B[K,N], row-major, all dims multiples of 128 and
// K multiple of 8. 128x128 block tile, BK=8, 256 threads, 8x8 per thread,
// register prefetch of the next global tile.
// ---------------------------------------------------------------------------
__global__ __launch_bounds__(256) void sgemm128(const float* __restrict__ A,
                                                const float* __restrict__ B,
                                                float* __restrict__ C,
                                                int M, int N, int K) {
    __shared__ float As[8][128];
    __shared__ float Bs[8][128];

    int tid = threadIdx.x;
    int ty = tid >> 4;        // 0..15
    int tx = tid & 15;        // 0..15

    const float* Ab = A + (size_t)blockIdx.y * 128 * K;
    const float* Bb = B + (size_t)blockIdx.x * 128;
    float* Cb = C + (size_t)blockIdx.y * 128 * N + (size_t)blockIdx.x * 128;

    int ar = tid >> 1;             // 0..127
    int ac = (tid & 1) * 4;        // 0 or 4
    int br = tid >> 5;             // 0..7
    int bc = (tid & 31) * 4;       // 0..124

    float acc[8][8];
#pragma unroll
    for (int i = 0; i < 8; i++)
#pragma unroll
        for (int j = 0; j < 8; j++) acc[i][j] = 0.f;

    float4 av = *(const float4*)(Ab + (size_t)ar * K + ac);
    float4 bv = *(const float4*)(Bb + (size_t)br * N + bc);

    for (int k0 = 0; k0 < K; k0 += 8) {
        // stage current tile to smem
        As[ac + 0][ar] = av.x;
        As[ac + 1][ar] = av.y;
        As[ac + 2][ar] = av.z;
        As[ac + 3][ar] = av.w;
        *(float4*)(&Bs[br][bc]) = bv;
        __syncthreads();

        // prefetch next tile into registers (overlaps with compute below)
        if (k0 + 8 < K) {
            av = *(const float4*)(Ab + (size_t)ar * K + (k0 + 8) + ac);
            bv = *(const float4*)(Bb + (size_t)(k0 + 8 + br) * N + bc);
        }

#pragma unroll
        for (int k = 0; k < 8; k++) {
            float a[8], b[8];
            *(float4*)(a)     = *(const float4*)(&As[k][ty * 8]);
            *(float4*)(a + 4) = *(const float4*)(&As[k][ty * 8 + 4]);
            *(float4*)(b)     = *(const float4*)(&Bs[k][tx * 8]);
            *(float4*)(b + 4) = *(const float4*)(&Bs[k][tx * 8 + 4]);
#pragma unroll
            for (int i = 0; i < 8; i++)
#pragma unroll
                for (int j = 0; j < 8; j++) acc[i][j] += a[i] * b[j];
        }
        __syncthreads();
    }

#pragma unroll
    for (int i = 0; i < 8; i++) {
#pragma unroll
        for (int j = 0; j < 8; j += 4) {
            float4 v = make_float4(acc[i][j], acc[i][j + 1], acc[i][j + 2],
                                   acc[i][j + 3]);
            *(float4*)(Cb + (size_t)(ty * 8 + i) * N + tx * 8 + j) = v;
        }
    }
}

// ---------------------------------------------------------------------------
// Causal GQA flash attention (fp32).
// Block = (q tile of 64, one q head). 256 threads.
// Smem: Qs[64x128], Ks[64x129] (pad -> 2-way LDS conflicts max), Vs[64x128],
//       Ss[64x65], row stats. ~113 KB dynamic.
// Thread (ty,tx) 16x16 grid owns score micro-tile [4x4] and acc rows
// ty*4+a (a<4), dims tx*8+c (c<8).
// ---------------------------------------------------------------------------
#define FLASH_SMEM_FLOATS (64*128 + 64*129 + 64*128 + 64*65 + 3*64)
#define FLASH_SMEM_BYTES  (FLASH_SMEM_FLOATS * 4)

__global__ __launch_bounds__(256) void flash_kernel(const float* __restrict__ qkv,
                                                    float* __restrict__ out) {
    extern __shared__ float sm[];
    float* Qs   = sm;                   // 64*128
    float* Ks   = Qs + 64 * 128;        // 64*129
    float* Vs   = Ks + 64 * 129;        // 64*128
    float* Ss   = Vs + 64 * 128;        // 64*65
    float* mrow = Ss + 64 * 65;         // 64
    float* lrow = mrow + 64;            // 64
    float* srow = lrow + 64;            // 64

    int qb = blockIdx.x;   // 0..31
    int hq = blockIdx.y;   // 0..31
    int hk = hq >> 2;      // GQA: kv head = hq / 4
    int tid = threadIdx.x;
    int ty = tid >> 4;
    int tx = tid & 15;
    const float scale = 0.08838834764831843f;  // 1/sqrt(128)

    // load Q tile
    const float* qbase = qkv + (size_t)qb * 64 * QKV_W + hq * HD;
#pragma unroll
    for (int it = 0; it < 8; it++) {
        int idx = tid + it * 256;     // 0..2047 float4 slots
        int r = idx >> 5;
        int c4 = (idx & 31) * 4;
        *(float4*)(Qs + r * 128 + c4) =
            *(const float4*)(qbase + (size_t)r * QKV_W + c4);
    }
    if (tid < 64) {
        mrow[tid] = -INFINITY;
        lrow[tid] = 0.f;
    }

    float acc[4][8];
#pragma unroll
    for (int a = 0; a < 4; a++)
#pragma unroll
        for (int c = 0; c < 8; c++) acc[a][c] = 0.f;
    __syncthreads();

    for (int kt = 0; kt <= qb; kt++) {
        const float* kbase = qkv + (size_t)kt * 64 * QKV_W + NH * HD + hk * HD;
        const float* vbase = kbase + NKV * HD;
#pragma unroll
        for (int it = 0; it < 8; it++) {
            int idx = tid + it * 256;
            int r = idx >> 5;
            int c4 = (idx & 31) * 4;
            float4 kv = *(const float4*)(kbase + (size_t)r * QKV_W + c4);
            float4 vv = *(const float4*)(vbase + (size_t)r * QKV_W + c4);
            Ks[r * 129 + c4 + 0] = kv.x;
            Ks[r * 129 + c4 + 1] = kv.y;
            Ks[r * 129 + c4 + 2] = kv.z;
            Ks[r * 129 + c4 + 3] = kv.w;
            *(float4*)(Vs + r * 128 + c4) = vv;
        }
        __syncthreads();

        // ---- scores: S[4x4] micro-tile per thread ----
        float s[4][4];
#pragma unroll
        for (int a = 0; a < 4; a++)
#pragma unroll
            for (int b = 0; b < 4; b++) s[a][b] = 0.f;

#pragma unroll 4
        for (int d = 0; d < 128; d++) {
            float qv[4], kv[4];
#pragma unroll
            for (int a = 0; a < 4; a++) qv[a] = Qs[(ty * 4 + a) * 128 + d];
#pragma unroll
            for (int b = 0; b < 4; b++) kv[b] = Ks[(tx * 4 + b) * 129 + d];
#pragma unroll
            for (int a = 0; a < 4; a++)
#pragma unroll
                for (int b = 0; b < 4; b++) s[a][b] += qv[a] * kv[b];
        }
#pragma unroll
        for (int a = 0; a < 4; a++)
#pragma unroll
            for (int b = 0; b < 4; b++)
                Ss[(ty * 4 + a) * 65 + tx * 4 + b] = s[a][b] * scale;
        __syncthreads();

        // ---- online softmax: 4 threads per row ----
        {
            int r = tid >> 2;
            int sub = tid & 3;
            int jmax = (kt == qb) ? r : 63;   // causal: valid j <= qi - kt*64
            float m_old = mrow[r];
            float mloc = -INFINITY;
#pragma unroll
            for (int jj = 0; jj < 16; jj++) {
                int j = sub * 16 + jj;
                if (j <= jmax) mloc = fmaxf(mloc, Ss[r * 65 + j]);
            }
            mloc = fmaxf(mloc, __shfl_xor_sync(0xffffffffu, mloc, 1));
            mloc = fmaxf(mloc, __shfl_xor_sync(0xffffffffu, mloc, 2));
            float m_new = fmaxf(m_old, mloc);
            float sum = 0.f;
#pragma unroll
            for (int jj = 0; jj < 16; jj++) {
                int j = sub * 16 + jj;
                float p = (j <= jmax) ? expf(Ss[r * 65 + j] - m_new) : 0.f;
                Ss[r * 65 + j] = p;
                sum += p;
            }
            sum += __shfl_xor_sync(0xffffffffu, sum, 1);
            sum += __shfl_xor_sync(0xffffffffu, sum, 2);
            if (sub == 0) {
                float sc = expf(m_old - m_new);
                srow[r] = sc;
                lrow[r] = lrow[r] * sc + sum;
                mrow[r] = m_new;
            }
        }
        __syncthreads();

        // ---- rescale accumulators + P@V ----
        float sca[4];
#pragma unroll
        for (int a = 0; a < 4; a++) sca[a] = srow[ty * 4 + a];
#pragma unroll
        for (int a = 0; a < 4; a++)
#pragma unroll
            for (int c = 0; c < 8; c++) acc[a][c] *= sca[a];

#pragma unroll 2
        for (int j = 0; j < 64; j++) {
            float p[4];
#pragma unroll
            for (int a = 0; a < 4; a++) p[a] = Ss[(ty * 4 + a) * 65 + j];
            float4 v0 = *(const float4*)(Vs + j * 128 + tx * 8);
            float4 v1 = *(const float4*)(Vs + j * 128 + tx * 8 + 4);
#pragma unroll
            for (int a = 0; a < 4; a++) {
                acc[a][0] += p[a] * v0.x;
                acc[a][1] += p[a] * v0.y;
                acc[a][2] += p[a] * v0.z;
                acc[a][3] += p[a] * v0.w;
                acc[a][4] += p[a] * v1.x;
                acc[a][5] += p[a] * v1.y;
                acc[a][6] += p[a] * v1.z;
                acc[a][7] += p[a] * v1.w;
            }
        }
        __syncthreads();   // before next tile overwrites Ks/Vs/Ss
    }

    // ---- epilogue ----
#pragma unroll
    for (int a = 0; a < 4; a++) {
        float inv_l = 1.0f / lrow[ty * 4 + a];
        float4 o0 = make_float4(acc[a][0] * inv_l, acc[a][1] * inv_l,
                                acc[a][2] * inv_l, acc[a][3] * inv_l);
        float4 o1 = make_float4(acc[a][4] * inv_l, acc[a][5] * inv_l,
                                acc[a][6] * inv_l, acc[a][7] * inv_l);
        size_t row = (size_t)(qb * 64 + ty * 4 + a);
        *(float4*)(out + row * OUT_W + hq * HD + tx * 8)     = o0;
        *(float4*)(out + row * OUT_W + hq * HD + tx * 8 + 4) = o1;
    }
}

// ---------------------------------------------------------------------------
// launch
// ---------------------------------------------------------------------------
extern "C" void kernel_launch(void* const* d_in, const int* in_sizes, int n_in,
                              void* d_out, int out_size) {
    (void)in_sizes; (void)n_in; (void)out_size;
    const int*   positions = (const int*)d_in[0];
    const float* hidden    = (const float*)d_in[1];
    const float* Wqkv      = (const float*)d_in[2];
    const float* Wo        = (const float*)d_in[3];
    float*       out       = (float*)d_out;

    void* qkv_p  = nullptr;
    void* attn_p = nullptr;
    cudaGetSymbolAddress(&qkv_p, g_qkv);
    cudaGetSymbolAddress(&attn_p, g_attn);
    float* qkv  = (float*)qkv_p;
    float* attn = (float*)attn_p;

    cudaFuncSetAttribute(flash_kernel,
                         cudaFuncAttributeMaxDynamicSharedMemorySize,
                         FLASH_SMEM_BYTES);

    init_invfreq_kernel<<<1, 64>>>();

    // qkv = hidden @ Wqkv
    sgemm128<<<dim3(QKV_W / 128, T_TOK / 128), 256>>>(hidden, Wqkv, qkv,
                                                      T_TOK, QKV_W, HID);
    // RoPE on q + k heads
    rope_kernel<<<dim3(T_TOK, NH + NKV), 64>>>(positions, qkv);

    // flash attention
    flash_kernel<<<dim3(T_TOK / 64, NH), 256, FLASH_SMEM_BYTES>>>(qkv, attn);

    // out = attn @ Wo
    sgemm128<<<dim3(HID / 128, T_TOK / 128), 256>>>(attn, Wo, out,
                                                    T_TOK, HID, HID);
}

// round 2
// speedup vs baseline: 1.9256x; 1.9256x over previous
#include <cuda_runtime.h>
#include <cuda_bf16.h>
#include <math.h>

// Problem constants
#define T_TOK 2048
#define HID   4096
#define NH    32
#define NKV   8
#define HD    128
#define QKV_W ((NH + 2*NKV) * HD)   // 6144
#define OUT_W (NH * HD)             // 4096

// Scratch (allocation-free requirement -> device globals)
__device__ float g_qkv[(size_t)T_TOK * QKV_W];     // 50.3 MB
__device__ float g_attn[(size_t)T_TOK * OUT_W];    // 33.6 MB
__device__ float g_invfreq_pi[HD/2];

// ---------------------------------------------------------------------------
// inv_freq table (divided by pi -> cospif/sinpif, immune to fast-math remap)
// ---------------------------------------------------------------------------
__global__ void init_invfreq_kernel() {
    int i = threadIdx.x;  // 0..63
    double inv = pow(1.0e6, -((double)(2 * i)) / 128.0);
    g_invfreq_pi[i] = (float)(inv / 3.14159265358979323846);
}

// ---------------------------------------------------------------------------
// GPT-J interleaved RoPE in-place on q heads (0..31) and k heads (32..39)
// ---------------------------------------------------------------------------
__global__ void rope_kernel(const int* __restrict__ positions,
                            float* __restrict__ qkv) {
    int t = blockIdx.x;
    int h = blockIdx.y;        // 0..39
    int i = threadIdx.x;       // 0..63
    float pos = (float)positions[t];
    float f = pos * g_invfreq_pi[i];
    float c = cospif(f);
    float s = sinpif(f);
    float* base = qkv + (size_t)t * QKV_W + h * HD;
    float x1 = base[2 * i];
    float x2 = base[2 * i + 1];
    base[2 * i]     = x1 * c - x2 * s;
    base[2 * i + 1] = x2 * c + x1 * s;
}

// ---------------------------------------------------------------------------
// TF32 tensor-core GEMM: C[M,N] = A[M,K] @ B[K,N], row-major.
// M,N multiples of 128, K multiple of 16.
// 128x128x16 block tile, 256 threads (8 warps, 4x2), 32x64 per warp,
// mma.sync m16n8k8 tf32, double-buffered smem.
// ---------------------------------------------------------------------------
#define AS_STRIDE 20    // 16 + 4 pad -> conflict-free A fragment LDS
#define BS_STRIDE 136   // 128 + 8 pad -> conflict-free B fragment LDS

__device__ __forceinline__ unsigned f2tf32(float x) {
    unsigned u;
    asm("cvt.rna.tf32.f32 %0, %1;" : "=r"(u) : "f"(x));
    return u;
}

__device__ __forceinline__ float4 cvt4(float4 v) {
    float4 r;
    r.x = __uint_as_float(f2tf32(v.x));
    r.y = __uint_as_float(f2tf32(v.y));
    r.z = __uint_as_float(f2tf32(v.z));
    r.w = __uint_as_float(f2tf32(v.w));
    return r;
}

__device__ __forceinline__ void mma_tf32(float c[4], const unsigned a[4],
                                         unsigned b0, unsigned b1) {
    asm volatile(
        "mma.sync.aligned.m16n8k8.row.col.f32.tf32.tf32.f32 "
        "{%0,%1,%2,%3}, {%4,%5,%6,%7}, {%8,%9}, {%0,%1,%2,%3};\n"
        : "+f"(c[0]), "+f"(c[1]), "+f"(c[2]), "+f"(c[3])
        : "r"(a[0]), "r"(a[1]), "r"(a[2]), "r"(a[3]), "r"(b0), "r"(b1));
}

__global__ __launch_bounds__(256) void sgemm_tf32(const float* __restrict__ A,
                                                  const float* __restrict__ B,
                                                  float* __restrict__ C,
                                                  int M, int N, int K) {
    __shared__ float As[2][128 * AS_STRIDE];
    __shared__ float Bs[2][16 * BS_STRIDE];

    int tid = threadIdx.x;
    int warp = tid >> 5;
    int lane = tid & 31;
    int wm = warp >> 1;           // 0..3
    int wn = warp & 1;            // 0..1
    int m_warp = wm * 32;
    int n_warp = wn * 64;
    int gid = lane >> 2;          // 0..7
    int tig = lane & 3;           // 0..3

    const float* Ab = A + (size_t)blockIdx.y * 128 * K;
    const float* Bb = B + (size_t)blockIdx.x * 128;
    float* Cb = C + (size_t)blockIdx.y * 128 * N + (size_t)blockIdx.x * 128;

    // staging coordinates
    int ar = tid >> 2;            // 0..63 (and +64)
    int ac = (tid & 3) * 4;       // 0,4,8,12
    int br = tid >> 5;            // 0..7 (and +8)
    int bc = (tid & 31) * 4;      // 0..124

    float acc[2][8][4];
#pragma unroll
    for (int mi = 0; mi < 2; mi++)
#pragma unroll
        for (int ni = 0; ni < 8; ni++)
#pragma unroll
            for (int q = 0; q < 4; q++) acc[mi][ni][q] = 0.f;

    // stage k0 = 0 into buffer 0
    {
        float4 a0 = *(const float4*)(Ab + (size_t)ar * K + ac);
        float4 a1 = *(const float4*)(Ab + (size_t)(ar + 64) * K + ac);
        float4 b0 = *(const float4*)(Bb + (size_t)br * N + bc);
        float4 b1 = *(const float4*)(Bb + (size_t)(br + 8) * N + bc);
        *(float4*)(&As[0][ar * AS_STRIDE + ac])        = cvt4(a0);
        *(float4*)(&As[0][(ar + 64) * AS_STRIDE + ac]) = cvt4(a1);
        *(float4*)(&Bs[0][br * BS_STRIDE + bc])        = cvt4(b0);
        *(float4*)(&Bs[0][(br + 8) * BS_STRIDE + bc])  = cvt4(b1);
    }
    __syncthreads();

    int cur = 0;
    for (int k0 = 0; k0 < K; k0 += 16) {
        bool has_next = (k0 + 16) < K;
        float4 pa0, pa1, pb0, pb1;
        if (has_next) {
            int kn = k0 + 16;
            pa0 = *(const float4*)(Ab + (size_t)ar * K + kn + ac);
            pa1 = *(const float4*)(Ab + (size_t)(ar + 64) * K + kn + ac);
            pb0 = *(const float4*)(Bb + (size_t)(kn + br) * N + bc);
            pb1 = *(const float4*)(Bb + (size_t)(kn + br + 8) * N + bc);
        }

        const float* Ac = As[cur];
        const float* Bc = Bs[cur];
#pragma unroll
        for (int ks = 0; ks < 16; ks += 8) {
            unsigned af[2][4];
#pragma unroll
            for (int mi = 0; mi < 2; mi++) {
                int m0 = m_warp + mi * 16;
                af[mi][0] = __float_as_uint(Ac[(m0 + gid) * AS_STRIDE + ks + tig]);
                af[mi][1] = __float_as_uint(Ac[(m0 + gid + 8) * AS_STRIDE + ks + tig]);
                af[mi][2] = __float_as_uint(Ac[(m0 + gid) * AS_STRIDE + ks + tig + 4]);
                af[mi][3] = __float_as_uint(Ac[(m0 + gid + 8) * AS_STRIDE + ks + tig + 4]);
            }
#pragma unroll
            for (int ni = 0; ni < 8; ni++) {
                int n0 = n_warp + ni * 8;
                unsigned b0 = __float_as_uint(Bc[(ks + tig) * BS_STRIDE + n0 + gid]);
                unsigned b1 = __float_as_uint(Bc[(ks + tig + 4) * BS_STRIDE + n0 + gid]);
                mma_tf32(acc[0][ni], af[0], b0, b1);
                mma_tf32(acc[1][ni], af[1], b0, b1);
            }
        }

        if (has_next) {
            int nxt = cur ^ 1;
            *(float4*)(&As[nxt][ar * AS_STRIDE + ac])        = cvt4(pa0);
            *(float4*)(&As[nxt][(ar + 64) * AS_STRIDE + ac]) = cvt4(pa1);
            *(float4*)(&Bs[nxt][br * BS_STRIDE + bc])        = cvt4(pb0);
            *(float4*)(&Bs[nxt][(br + 8) * BS_STRIDE + bc])  = cvt4(pb1);
            __syncthreads();
            cur = nxt;
        }
    }

    // epilogue
#pragma unroll
    for (int mi = 0; mi < 2; mi++) {
#pragma unroll
        for (int ni = 0; ni < 8; ni++) {
            int row0 = m_warp + mi * 16 + gid;
            int col  = n_warp + ni * 8 + tig * 2;
            *(float2*)(Cb + (size_t)row0 * N + col) =
                make_float2(acc[mi][ni][0], acc[mi][ni][1]);
            *(float2*)(Cb + (size_t)(row0 + 8) * N + col) =
                make_float2(acc[mi][ni][2], acc[mi][ni][3]);
        }
    }
}

// ---------------------------------------------------------------------------
// Causal GQA flash attention (fp32) — unchanged from round 0.
// ---------------------------------------------------------------------------
#define FLASH_SMEM_FLOATS (64*128 + 64*129 + 64*128 + 64*65 + 3*64)
#define FLASH_SMEM_BYTES  (FLASH_SMEM_FLOATS * 4)

__global__ __launch_bounds__(256) void flash_kernel(const float* __restrict__ qkv,
                                                    float* __restrict__ out) {
    extern __shared__ float sm[];
    float* Qs   = sm;                   // 64*128
    float* Ks   = Qs + 64 * 128;        // 64*129
    float* Vs   = Ks + 64 * 129;        // 64*128
    float* Ss   = Vs + 64 * 128;        // 64*65
    float* mrow = Ss + 64 * 65;         // 64
    float* lrow = mrow + 64;            // 64
    float* srow = lrow + 64;            // 64

    int qb = blockIdx.x;   // 0..31
    int hq = blockIdx.y;   // 0..31
    int hk = hq >> 2;      // GQA
    int tid = threadIdx.x;
    int ty = tid >> 4;
    int tx = tid & 15;
    const float scale = 0.08838834764831843f;  // 1/sqrt(128)

    const float* qbase = qkv + (size_t)qb * 64 * QKV_W + hq * HD;
#pragma unroll
    for (int it = 0; it < 8; it++) {
        int idx = tid + it * 256;
        int r = idx >> 5;
        int c4 = (idx & 31) * 4;
        *(float4*)(Qs + r * 128 + c4) =
            *(const float4*)(qbase + (size_t)r * QKV_W + c4);
    }
    if (tid < 64) {
        mrow[tid] = -INFINITY;
        lrow[tid] = 0.f;
    }

    float acc[4][8];
#pragma unroll
    for (int a = 0; a < 4; a++)
#pragma unroll
        for (int c = 0; c < 8; c++) acc[a][c] = 0.f;
    __syncthreads();

    for (int kt = 0; kt <= qb; kt++) {
        const float* kbase = qkv + (size_t)kt * 64 * QKV_W + NH * HD + hk * HD;
        const float* vbase = kbase + NKV * HD;
#pragma unroll
        for (int it = 0; it < 8; it++) {
            int idx = tid + it * 256;
            int r = idx >> 5;
            int c4 = (idx & 31) * 4;
            float4 kv = *(const float4*)(kbase + (size_t)r * QKV_W + c4);
            float4 vv = *(const float4*)(vbase + (size_t)r * QKV_W + c4);
            Ks[r * 129 + c4 + 0] = kv.x;
            Ks[r * 129 + c4 + 1] = kv.y;
            Ks[r * 129 + c4 + 2] = kv.z;
            Ks[r * 129 + c4 + 3] = kv.w;
            *(float4*)(Vs + r * 128 + c4) = vv;
        }
        __syncthreads();

        float s[4][4];
#pragma unroll
        for (int a = 0; a < 4; a++)
#pragma unroll
            for (int b = 0; b < 4; b++) s[a][b] = 0.f;

#pragma unroll 4
        for (int d = 0; d < 128; d++) {
            float qv[4], kv[4];
#pragma unroll
            for (int a = 0; a < 4; a++) qv[a] = Qs[(ty * 4 + a) * 128 + d];
#pragma unroll
            for (int b = 0; b < 4; b++) kv[b] = Ks[(tx * 4 + b) * 129 + d];
#pragma unroll
            for (int a = 0; a < 4; a++)
#pragma unroll
                for (int b = 0; b < 4; b++) s[a][b] += qv[a] * kv[b];
        }
#pragma unroll
        for (int a = 0; a < 4; a++)
#pragma unroll
            for (int b = 0; b < 4; b++)
                Ss[(ty * 4 + a) * 65 + tx * 4 + b] = s[a][b] * scale;
        __syncthreads();

        {
            int r = tid >> 2;
            int sub = tid & 3;
            int jmax = (kt == qb) ? r : 63;
            float m_old = mrow[r];
            float mloc = -INFINITY;
#pragma unroll
            for (int jj = 0; jj < 16; jj++) {
                int j = sub * 16 + jj;
                if (j <= jmax) mloc = fmaxf(mloc, Ss[r * 65 + j]);
            }
            mloc = fmaxf(mloc, __shfl_xor_sync(0xffffffffu, mloc, 1));
            mloc = fmaxf(mloc, __shfl_xor_sync(0xffffffffu, mloc, 2));
            float m_new = fmaxf(m_old, mloc);
            float sum = 0.f;
#pragma unroll
            for (int jj = 0; jj < 16; jj++) {
                int j = sub * 16 + jj;
                float p = (j <= jmax) ? expf(Ss[r * 65 + j] - m_new) : 0.f;
                Ss[r * 65 + j] = p;
                sum += p;
            }
            sum += __shfl_xor_sync(0xffffffffu, sum, 1);
            sum += __shfl_xor_sync(0xffffffffu, sum, 2);
            if (sub == 0) {
                float sc = expf(m_old - m_new);
                srow[r] = sc;
                lrow[r] = lrow[r] * sc + sum;
                mrow[r] = m_new;
            }
        }
        __syncthreads();

        float sca[4];
#pragma unroll
        for (int a = 0; a < 4; a++) sca[a] = srow[ty * 4 + a];
#pragma unroll
        for (int a = 0; a < 4; a++)
#pragma unroll
            for (int c = 0; c < 8; c++) acc[a][c] *= sca[a];

#pragma unroll 2
        for (int j = 0; j < 64; j++) {
            float p[4];
#pragma unroll
            for (int a = 0; a < 4; a++) p[a] = Ss[(ty * 4 + a) * 65 + j];
            float4 v0 = *(const float4*)(Vs + j * 128 + tx * 8);
            float4 v1 = *(const float4*)(Vs + j * 128 + tx * 8 + 4);
#pragma unroll
            for (int a = 0; a < 4; a++) {
                acc[a][0] += p[a] * v0.x;
                acc[a][1] += p[a] * v0.y;
                acc[a][2] += p[a] * v0.z;
                acc[a][3] += p[a] * v0.w;
                acc[a][4] += p[a] * v1.x;
                acc[a][5] += p[a] * v1.y;
                acc[a][6] += p[a] * v1.z;
                acc[a][7] += p[a] * v1.w;
            }
        }
        __syncthreads();
    }

#pragma unroll
    for (int a = 0; a < 4; a++) {
        float inv_l = 1.0f / lrow[ty * 4 + a];
        float4 o0 = make_float4(acc[a][0] * inv_l, acc[a][1] * inv_l,
                                acc[a][2] * inv_l, acc[a][3] * inv_l);
        float4 o1 = make_float4(acc[a][4] * inv_l, acc[a][5] * inv_l,
                                acc[a][6] * inv_l, acc[a][7] * inv_l);
        size_t row = (size_t)(qb * 64 + ty * 4 + a);
        *(float4*)(out + row * OUT_W + hq * HD + tx * 8)     = o0;
        *(float4*)(out + row * OUT_W + hq * HD + tx * 8 + 4) = o1;
    }
}

// ---------------------------------------------------------------------------
// launch
// ---------------------------------------------------------------------------
extern "C" void kernel_launch(void* const* d_in, const int* in_sizes, int n_in,
                              void* d_out, int out_size) {
    (void)in_sizes; (void)n_in; (void)out_size;
    const int*   positions = (const int*)d_in[0];
    const float* hidden    = (const float*)d_in[1];
    const float* Wqkv      = (const float*)d_in[2];
    const float* Wo        = (const float*)d_in[3];
    float*       out       = (float*)d_out;

    void* qkv_p  = nullptr;
    void* attn_p = nullptr;
    cudaGetSymbolAddress(&qkv_p, g_qkv);
    cudaGetSymbolAddress(&attn_p, g_attn);
    float* qkv  = (float*)qkv_p;
    float* attn = (float*)attn_p;

    cudaFuncSetAttribute(flash_kernel,
                         cudaFuncAttributeMaxDynamicSharedMemorySize,
                         FLASH_SMEM_BYTES);

    init_invfreq_kernel<<<1, 64>>>();

    // qkv = hidden @ Wqkv  (tf32 tensor cores)
    sgemm_tf32<<<dim3(QKV_W / 128, T_TOK / 128), 256>>>(hidden, Wqkv, qkv,
                                                        T_TOK, QKV_W, HID);
    // RoPE on q + k heads
    rope_kernel<<<dim3(T_TOK, NH + NKV), 64>>>(positions, qkv);

    // flash attention
    flash_kernel<<<dim3(T_TOK / 64, NH), 256, FLASH_SMEM_BYTES>>>(qkv, attn);

    // out = attn @ Wo  (tf32 tensor cores)
    sgemm_tf32<<<dim3(HID / 128, T_TOK / 128), 256>>>(attn, Wo, out,
                                                      T_TOK, HID, HID);
}

// round 3
// speedup vs baseline: 2.8626x; 1.4866x over previous
#include <cuda_runtime.h>
#include <cuda_fp16.h>
#include <cuda_bf16.h>
#include <math.h>

// Problem constants
#define T_TOK 2048
#define HID   4096
#define NH    32
#define NKV   8
#define HD    128
#define QKV_W ((NH + 2*NKV) * HD)   // 6144
#define OUT_W (NH * HD)             // 4096
#define SM_SCALE 0.08838834764831843f  // 1/sqrt(128)

// Scratch (allocation-free requirement -> device globals)
__device__ float g_qkv[(size_t)T_TOK * QKV_W];     // 50.3 MB
__device__ float g_attn[(size_t)T_TOK * OUT_W];    // 33.6 MB
__device__ float g_invfreq_pi[HD/2];

// ---------------------------------------------------------------------------
// inv_freq table (divided by pi -> cospif/sinpif, immune to fast-math remap)
// ---------------------------------------------------------------------------
__global__ void init_invfreq_kernel() {
    int i = threadIdx.x;  // 0..63
    double inv = pow(1.0e6, -((double)(2 * i)) / 128.0);
    g_invfreq_pi[i] = (float)(inv / 3.14159265358979323846);
}

// ---------------------------------------------------------------------------
// GPT-J interleaved RoPE in-place on q heads (0..31) and k heads (32..39)
// ---------------------------------------------------------------------------
__global__ void rope_kernel(const int* __restrict__ positions,
                            float* __restrict__ qkv) {
    int t = blockIdx.x;
    int h = blockIdx.y;        // 0..39
    int i = threadIdx.x;       // 0..63
    float pos = (float)positions[t];
    float f = pos * g_invfreq_pi[i];
    float c = cospif(f);
    float s = sinpif(f);
    float* base = qkv + (size_t)t * QKV_W + h * HD;
    float x1 = base[2 * i];
    float x2 = base[2 * i + 1];
    base[2 * i]     = x1 * c - x2 * s;
    base[2 * i + 1] = x2 * c + x1 * s;
}

// ---------------------------------------------------------------------------
// TF32 tensor-core GEMM (unchanged from round 2)
// ---------------------------------------------------------------------------
#define AS_STRIDE 20
#define BS_STRIDE 136

__device__ __forceinline__ unsigned f2tf32(float x) {
    unsigned u;
    asm("cvt.rna.tf32.f32 %0, %1;" : "=r"(u) : "f"(x));
    return u;
}

__device__ __forceinline__ float4 cvt4(float4 v) {
    float4 r;
    r.x = __uint_as_float(f2tf32(v.x));
    r.y = __uint_as_float(f2tf32(v.y));
    r.z = __uint_as_float(f2tf32(v.z));
    r.w = __uint_as_float(f2tf32(v.w));
    return r;
}

__device__ __forceinline__ void mma_tf32(float c[4], const unsigned a[4],
                                         unsigned b0, unsigned b1) {
    asm volatile(
        "mma.sync.aligned.m16n8k8.row.col.f32.tf32.tf32.f32 "
        "{%0,%1,%2,%3}, {%4,%5,%6,%7}, {%8,%9}, {%0,%1,%2,%3};\n"
        : "+f"(c[0]), "+f"(c[1]), "+f"(c[2]), "+f"(c[3])
        : "r"(a[0]), "r"(a[1]), "r"(a[2]), "r"(a[3]), "r"(b0), "r"(b1));
}

__global__ __launch_bounds__(256) void sgemm_tf32(const float* __restrict__ A,
                                                  const float* __restrict__ B,
                                                  float* __restrict__ C,
                                                  int M, int N, int K) {
    __shared__ float As[2][128 * AS_STRIDE];
    __shared__ float Bs[2][16 * BS_STRIDE];

    int tid = threadIdx.x;
    int warp = tid >> 5;
    int lane = tid & 31;
    int wm = warp >> 1;
    int wn = warp & 1;
    int m_warp = wm * 32;
    int n_warp = wn * 64;
    int gid = lane >> 2;
    int tig = lane & 3;

    const float* Ab = A + (size_t)blockIdx.y * 128 * K;
    const float* Bb = B + (size_t)blockIdx.x * 128;
    float* Cb = C + (size_t)blockIdx.y * 128 * N + (size_t)blockIdx.x * 128;

    int ar = tid >> 2;
    int ac = (tid & 3) * 4;
    int br = tid >> 5;
    int bc = (tid & 31) * 4;

    float acc[2][8][4];
#pragma unroll
    for (int mi = 0; mi < 2; mi++)
#pragma unroll
        for (int ni = 0; ni < 8; ni++)
#pragma unroll
            for (int q = 0; q < 4; q++) acc[mi][ni][q] = 0.f;

    {
        float4 a0 = *(const float4*)(Ab + (size_t)ar * K + ac);
        float4 a1 = *(const float4*)(Ab + (size_t)(ar + 64) * K + ac);
        float4 b0 = *(const float4*)(Bb + (size_t)br * N + bc);
        float4 b1 = *(const float4*)(Bb + (size_t)(br + 8) * N + bc);
        *(float4*)(&As[0][ar * AS_STRIDE + ac])        = cvt4(a0);
        *(float4*)(&As[0][(ar + 64) * AS_STRIDE + ac]) = cvt4(a1);
        *(float4*)(&Bs[0][br * BS_STRIDE + bc])        = cvt4(b0);
        *(float4*)(&Bs[0][(br + 8) * BS_STRIDE + bc])  = cvt4(b1);
    }
    __syncthreads();

    int cur = 0;
    for (int k0 = 0; k0 < K; k0 += 16) {
        bool has_next = (k0 + 16) < K;
        float4 pa0, pa1, pb0, pb1;
        if (has_next) {
            int kn = k0 + 16;
            pa0 = *(const float4*)(Ab + (size_t)ar * K + kn + ac);
            pa1 = *(const float4*)(Ab + (size_t)(ar + 64) * K + kn + ac);
            pb0 = *(const float4*)(Bb + (size_t)(kn + br) * N + bc);
            pb1 = *(const float4*)(Bb + (size_t)(kn + br + 8) * N + bc);
        }

        const float* Ac = As[cur];
        const float* Bc = Bs[cur];
#pragma unroll
        for (int ks = 0; ks < 16; ks += 8) {
            unsigned af[2][4];
#pragma unroll
            for (int mi = 0; mi < 2; mi++) {
                int m0 = m_warp + mi * 16;
                af[mi][0] = __float_as_uint(Ac[(m0 + gid) * AS_STRIDE + ks + tig]);
                af[mi][1] = __float_as_uint(Ac[(m0 + gid + 8) * AS_STRIDE + ks + tig]);
                af[mi][2] = __float_as_uint(Ac[(m0 + gid) * AS_STRIDE + ks + tig + 4]);
                af[mi][3] = __float_as_uint(Ac[(m0 + gid + 8) * AS_STRIDE + ks + tig + 4]);
            }
#pragma unroll
            for (int ni = 0; ni < 8; ni++) {
                int n0 = n_warp + ni * 8;
                unsigned b0 = __float_as_uint(Bc[(ks + tig) * BS_STRIDE + n0 + gid]);
                unsigned b1 = __float_as_uint(Bc[(ks + tig + 4) * BS_STRIDE + n0 + gid]);
                mma_tf32(acc[0][ni], af[0], b0, b1);
                mma_tf32(acc[1][ni], af[1], b0, b1);
            }
        }

        if (has_next) {
            int nxt = cur ^ 1;
            *(float4*)(&As[nxt][ar * AS_STRIDE + ac])        = cvt4(pa0);
            *(float4*)(&As[nxt][(ar + 64) * AS_STRIDE + ac]) = cvt4(pa1);
            *(float4*)(&Bs[nxt][br * BS_STRIDE + bc])        = cvt4(pb0);
            *(float4*)(&Bs[nxt][(br + 8) * BS_STRIDE + bc])  = cvt4(pb1);
            __syncthreads();
            cur = nxt;
        }
    }

#pragma unroll
    for (int mi = 0; mi < 2; mi++) {
#pragma unroll
        for (int ni = 0; ni < 8; ni++) {
            int row0 = m_warp + mi * 16 + gid;
            int col  = n_warp + ni * 8 + tig * 2;
            *(float2*)(Cb + (size_t)row0 * N + col) =
                make_float2(acc[mi][ni][0], acc[mi][ni][1]);
            *(float2*)(Cb + (size_t)(row0 + 8) * N + col) =
                make_float2(acc[mi][ni][2], acc[mi][ni][3]);
        }
    }
}

// ---------------------------------------------------------------------------
// Flash attention v2: fp16 tensor cores with 3x hi/lo split (fp32-accurate).
// BQ=128 q rows per block, BK=64 k cols per tile, 256 threads (8 warps),
// warp owns 16 q rows x all 64 cols. Online softmax in registers.
//
// smem word (uint32) layout:
//   QH[2][128][68]  hi/lo planes of Q (half2 packed along d), scaled by SM_SCALE
//   KH[2][64][68]   hi/lo planes of K
//   VT[2][128][36]  hi/lo planes of V TRANSPOSED (row d, half2 packed along j)
//   PH[2][128][36]  hi/lo planes of P (half2 packed along j); the fp32 V
//                   staging buffer (64x132 floats) aliases this region.
// ---------------------------------------------------------------------------
#define QK_STR 68
#define VT_STR 36
#define PH_STR 36
#define VS_STR 132

#define QH0_OFF 0
#define QH1_OFF (128*QK_STR)                 // 8704
#define KH0_OFF (QH1_OFF + 128*QK_STR)       // 17408
#define KH1_OFF (KH0_OFF + 64*QK_STR)        // 21760
#define VT0_OFF (KH1_OFF + 64*QK_STR)        // 26112
#define VT1_OFF (VT0_OFF + 128*VT_STR)       // 30720
#define PH0_OFF (VT1_OFF + 128*VT_STR)       // 35328
#define PH1_OFF (PH0_OFF + 128*PH_STR)       // 39936
#define FLASH16_SMEM_WORDS (PH1_OFF + 128*PH_STR)   // 44544
#define FLASH16_SMEM_BYTES (FLASH16_SMEM_WORDS * 4) // 178176

__device__ __forceinline__ unsigned pack_hl(float x, float y) {
    __half hx = __float2half_rn(x);
    __half hy = __float2half_rn(y);
    return (unsigned)__half_as_ushort(hx) | ((unsigned)__half_as_ushort(hy) << 16);
}

// split a float into fp16 hi + fp16 lo planes, packed pairwise
__device__ __forceinline__ void split2(float x, float y, unsigned& hi, unsigned& lo) {
    __half hx = __float2half_rn(x);
    __half hy = __float2half_rn(y);
    float rx = x - __half2float(hx);
    float ry = y - __half2float(hy);
    hi = (unsigned)__half_as_ushort(hx) | ((unsigned)__half_as_ushort(hy) << 16);
    lo = (unsigned)__half_as_ushort(__float2half_rn(rx)) |
         ((unsigned)__half_as_ushort(__float2half_rn(ry)) << 16);
}

__device__ __forceinline__ void mma16(float c[4], unsigned a0, unsigned a1,
                                      unsigned a2, unsigned a3,
                                      unsigned b0, unsigned b1) {
    asm volatile(
        "mma.sync.aligned.m16n8k16.row.col.f32.f16.f16.f32 "
        "{%0,%1,%2,%3}, {%4,%5,%6,%7}, {%8,%9}, {%0,%1,%2,%3};\n"
        : "+f"(c[0]), "+f"(c[1]), "+f"(c[2]), "+f"(c[3])
        : "r"(a0), "r"(a1), "r"(a2), "r"(a3), "r"(b0), "r"(b1));
}

__global__ __launch_bounds__(256) void flash16_kernel(const float* __restrict__ qkv,
                                                      float* __restrict__ out) {
    extern __shared__ unsigned sw[];
    unsigned* QH0 = sw + QH0_OFF;
    unsigned* QH1 = sw + QH1_OFF;
    unsigned* KH0 = sw + KH0_OFF;
    unsigned* KH1 = sw + KH1_OFF;
    unsigned* VT0 = sw + VT0_OFF;
    unsigned* VT1 = sw + VT1_OFF;
    unsigned* PH0 = sw + PH0_OFF;
    unsigned* PH1 = sw + PH1_OFF;
    float* Vst = (float*)(sw + PH0_OFF);   // fp32 V staging, aliases P region

    int qb = gridDim.x - 1 - blockIdx.x;   // heavy blocks first
    int hq = blockIdx.y;
    int hk = hq >> 2;
    int tid = threadIdx.x;
    int warp = tid >> 5;
    int lane = tid & 31;
    int gid = lane >> 2;
    int tig = lane & 3;
    int m0 = warp * 16;

    // ---- stage Q (once), scaled by SM_SCALE, hi/lo split ----
    const float* qbase = qkv + (size_t)qb * 128 * QKV_W + hq * HD;
#pragma unroll
    for (int it = 0; it < 16; it++) {
        int idx = tid + it * 256;          // 0..4095
        int r = idx >> 5;                  // 0..127
        int c4 = (idx & 31) * 4;           // 0..124
        float4 q = *(const float4*)(qbase + (size_t)r * QKV_W + c4);
        q.x *= SM_SCALE; q.y *= SM_SCALE; q.z *= SM_SCALE; q.w *= SM_SCALE;
        unsigned h0, l0, h1, l1;
        split2(q.x, q.y, h0, l0);
        split2(q.z, q.w, h1, l1);
        int dw = c4 >> 1;
        QH0[r * QK_STR + dw]     = h0;
        QH0[r * QK_STR + dw + 1] = h1;
        QH1[r * QK_STR + dw]     = l0;
        QH1[r * QK_STR + dw + 1] = l1;
    }

    // per-row softmax state (rows m0+gid and m0+gid+8)
    float mprev0 = -1e30f, mprev1 = -1e30f;
    float lsum0 = 0.f, lsum1 = 0.f;
    float acco[16][4];
#pragma unroll
    for (int dt = 0; dt < 16; dt++)
#pragma unroll
        for (int q = 0; q < 4; q++) acco[dt][q] = 0.f;

    int grow0 = qb * 128 + m0 + gid;
    int grow1 = grow0 + 8;

    int nkt = 2 * qb + 2;
    for (int kt = 0; kt < nkt; kt++) {
        __syncthreads();   // prior iteration's reads done before restaging

        // ---- stage K (hi/lo) and V (fp32) ----
        const float* kbase = qkv + (size_t)kt * 64 * QKV_W + NH * HD + hk * HD;
        const float* vbase = kbase + NKV * HD;
#pragma unroll
        for (int it = 0; it < 8; it++) {
            int idx = tid + it * 256;      // 0..2047
            int r = idx >> 5;              // 0..63
            int c4 = (idx & 31) * 4;
            float4 k = *(const float4*)(kbase + (size_t)r * QKV_W + c4);
            unsigned h0, l0, h1, l1;
            split2(k.x, k.y, h0, l0);
            split2(k.z, k.w, h1, l1);
            int dw = c4 >> 1;
            KH0[r * QK_STR + dw]     = h0;
            KH0[r * QK_STR + dw + 1] = h1;
            KH1[r * QK_STR + dw]     = l0;
            KH1[r * QK_STR + dw + 1] = l1;
            float4 v = *(const float4*)(vbase + (size_t)r * QKV_W + c4);
            *(float4*)(Vst + r * VS_STR + c4) = v;
        }
        __syncthreads();

        // ---- transpose V into VT (hi/lo), pack pairs along j ----
#pragma unroll
        for (int it = 0; it < 16; it++) {
            int linear = tid + it * 256;   // 0..4095
            int jw = linear >> 7;          // 0..31
            int d = linear & 127;          // 0..127
            float v0 = Vst[(2 * jw) * VS_STR + d];
            float v1 = Vst[(2 * jw + 1) * VS_STR + d];
            unsigned hi, lo;
            split2(v0, v1, hi, lo);
            VT0[d * VT_STR + jw] = hi;
            VT1[d * VT_STR + jw] = lo;
        }
        __syncthreads();

        // ---- S = Q K^T (3x fp16 split), accumulate fp32 ----
        float accs[8][4];
#pragma unroll
        for (int nt = 0; nt < 8; nt++)
#pragma unroll
            for (int q = 0; q < 4; q++) accs[nt][q] = 0.f;

#pragma unroll
        for (int ks = 0; ks < 8; ks++) {
            int abase = (m0 + gid) * QK_STR + ks * 8 + tig;
            unsigned a00 = QH0[abase];
            unsigned a01 = QH0[abase + 8 * QK_STR];
            unsigned a02 = QH0[abase + 4];
            unsigned a03 = QH0[abase + 8 * QK_STR + 4];
            unsigned a10 = QH1[abase];
            unsigned a11 = QH1[abase + 8 * QK_STR];
            unsigned a12 = QH1[abase + 4];
            unsigned a13 = QH1[abase + 8 * QK_STR + 4];
#pragma unroll
            for (int nt = 0; nt < 8; nt++) {
                int bb = (nt * 8 + gid) * QK_STR + ks * 8 + tig;
                unsigned b00 = KH0[bb];
                unsigned b01 = KH0[bb + 4];
                unsigned b10 = KH1[bb];
                unsigned b11 = KH1[bb + 4];
                mma16(accs[nt], a00, a01, a02, a03, b00, b01);  // hi*hi
                mma16(accs[nt], a00, a01, a02, a03, b10, b11);  // hi*lo
                mma16(accs[nt], a10, a11, a12, a13, b00, b01);  // lo*hi
            }
        }

        // ---- causal mask + online softmax (registers) ----
        int colb = kt * 64 + 2 * tig;
        float mx0 = -1e30f, mx1 = -1e30f;
#pragma unroll
        for (int nt = 0; nt < 8; nt++) {
            int c0 = colb + nt * 8;
            int c1 = c0 + 1;
            accs[nt][0] = (c0 <= grow0) ? accs[nt][0] : -1e30f;
            accs[nt][1] = (c1 <= grow0) ? accs[nt][1] : -1e30f;
            accs[nt][2] = (c0 <= grow1) ? accs[nt][2] : -1e30f;
            accs[nt][3] = (c1 <= grow1) ? accs[nt][3] : -1e30f;
            mx0 = fmaxf(mx0, fmaxf(accs[nt][0], accs[nt][1]));
            mx1 = fmaxf(mx1, fmaxf(accs[nt][2], accs[nt][3]));
        }
        mx0 = fmaxf(mx0, __shfl_xor_sync(0xffffffffu, mx0, 1));
        mx0 = fmaxf(mx0, __shfl_xor_sync(0xffffffffu, mx0, 2));
        mx1 = fmaxf(mx1, __shfl_xor_sync(0xffffffffu, mx1, 1));
        mx1 = fmaxf(mx1, __shfl_xor_sync(0xffffffffu, mx1, 2));

        float mn0 = fmaxf(mprev0, mx0);
        float mn1 = fmaxf(mprev1, mx1);
        float corr0 = __expf(mprev0 - mn0);
        float corr1 = __expf(mprev1 - mn1);
        mprev0 = mn0;
        mprev1 = mn1;

        float sum0 = 0.f, sum1 = 0.f;
#pragma unroll
        for (int nt = 0; nt < 8; nt++) {
            accs[nt][0] = __expf(accs[nt][0] - mn0);
            accs[nt][1] = __expf(accs[nt][1] - mn0);
            accs[nt][2] = __expf(accs[nt][2] - mn1);
            accs[nt][3] = __expf(accs[nt][3] - mn1);
            sum0 += accs[nt][0] + accs[nt][1];
            sum1 += accs[nt][2] + accs[nt][3];
        }
        sum0 += __shfl_xor_sync(0xffffffffu, sum0, 1);
        sum0 += __shfl_xor_sync(0xffffffffu, sum0, 2);
        sum1 += __shfl_xor_sync(0xffffffffu, sum1, 1);
        sum1 += __shfl_xor_sync(0xffffffffu, sum1, 2);
        lsum0 = lsum0 * corr0 + sum0;
        lsum1 = lsum1 * corr1 + sum1;

        // rescale O accumulators
#pragma unroll
        for (int dt = 0; dt < 16; dt++) {
            acco[dt][0] *= corr0;
            acco[dt][1] *= corr0;
            acco[dt][2] *= corr1;
            acco[dt][3] *= corr1;
        }

        // ---- write P hi/lo to smem (per-warp private slice) ----
#pragma unroll
        for (int nt = 0; nt < 8; nt++) {
            unsigned hi0, lo0, hi1, lo1;
            split2(accs[nt][0], accs[nt][1], hi0, lo0);
            split2(accs[nt][2], accs[nt][3], hi1, lo1);
            int w0 = (m0 + gid) * PH_STR + nt * 4 + tig;
            int w1 = (m0 + gid + 8) * PH_STR + nt * 4 + tig;
            PH0[w0] = hi0;
            PH1[w0] = lo0;
            PH0[w1] = hi1;
            PH1[w1] = lo1;
        }
        __syncwarp();

        // ---- O += P V (3x fp16 split) ----
#pragma unroll
        for (int ks = 0; ks < 4; ks++) {
            int abase = (m0 + gid) * PH_STR + ks * 8 + tig;
            unsigned a00 = PH0[abase];
            unsigned a01 = PH0[abase + 8 * PH_STR];
            unsigned a02 = PH0[abase + 4];
            unsigned a03 = PH0[abase + 8 * PH_STR + 4];
            unsigned a10 = PH1[abase];
            unsigned a11 = PH1[abase + 8 * PH_STR];
            unsigned a12 = PH1[abase + 4];
            unsigned a13 = PH1[abase + 8 * PH_STR + 4];
#pragma unroll
            for (int dt = 0; dt < 16; dt++) {
                int vb = (dt * 8 + gid) * VT_STR + ks * 8 + tig;
                unsigned b00 = VT0[vb];
                unsigned b01 = VT0[vb + 4];
                unsigned b10 = VT1[vb];
                unsigned b11 = VT1[vb + 4];
                mma16(acco[dt], a00, a01, a02, a03, b00, b01);  // hi*hi
                mma16(acco[dt], a00, a01, a02, a03, b10, b11);  // hi*lo
                mma16(acco[dt], a10, a11, a12, a13, b00, b01);  // lo*hi
            }
        }
    }

    // ---- epilogue ----
    float il0 = 1.0f / lsum0;
    float il1 = 1.0f / lsum1;
    float* o0 = out + (size_t)grow0 * OUT_W + hq * HD;
    float* o1 = out + (size_t)grow1 * OUT_W + hq * HD;
#pragma unroll
    for (int dt = 0; dt < 16; dt++) {
        int col = dt * 8 + 2 * tig;
        *(float2*)(o0 + col) = make_float2(acco[dt][0] * il0, acco[dt][1] * il0);
        *(float2*)(o1 + col) = make_float2(acco[dt][2] * il1, acco[dt][3] * il1);
    }
}

// ---------------------------------------------------------------------------
// launch
// ---------------------------------------------------------------------------
extern "C" void kernel_launch(void* const* d_in, const int* in_sizes, int n_in,
                              void* d_out, int out_size) {
    (void)in_sizes; (void)n_in; (void)out_size;
    const int*   positions = (const int*)d_in[0];
    const float* hidden    = (const float*)d_in[1];
    const float* Wqkv      = (const float*)d_in[2];
    const float* Wo        = (const float*)d_in[3];
    float*       out       = (float*)d_out;

    void* qkv_p  = nullptr;
    void* attn_p = nullptr;
    cudaGetSymbolAddress(&qkv_p, g_qkv);
    cudaGetSymbolAddress(&attn_p, g_attn);
    float* qkv  = (float*)qkv_p;
    float* attn = (float*)attn_p;

    cudaFuncSetAttribute(flash16_kernel,
                         cudaFuncAttributeMaxDynamicSharedMemorySize,
                         FLASH16_SMEM_BYTES);

    init_invfreq_kernel<<<1, 64>>>();

    // qkv = hidden @ Wqkv  (tf32 tensor cores)
    sgemm_tf32<<<dim3(QKV_W / 128, T_TOK / 128), 256>>>(hidden, Wqkv, qkv,
                                                        T_TOK, QKV_W, HID);
    // RoPE on q + k heads
    rope_kernel<<<dim3(T_TOK, NH + NKV), 64>>>(positions, qkv);

    // flash attention (fp16 3x tensor cores)
    flash16_kernel<<<dim3(T_TOK / 128, NH), 256, FLASH16_SMEM_BYTES>>>(qkv, attn);

    // out = attn @ Wo  (tf32 tensor cores)
    sgemm_tf32<<<dim3(HID / 128, T_TOK / 128), 256>>>(attn, Wo, out,
                                                      T_TOK, HID, HID);
}

// round 4
// speedup vs baseline: 4.2002x; 1.4672x over previous
#include <cuda_runtime.h>
#include <cuda_fp16.h>
#include <cuda_bf16.h>
#include <math.h>

// Problem constants
#define T_TOK 2048
#define HID   4096
#define NH    32
#define NKV   8
#define HD    128
#define QKV_W ((NH + 2*NKV) * HD)   // 6144
#define OUT_W (NH * HD)             // 4096
#define SM_SCALE 0.08838834764831843f  // 1/sqrt(128)

// Scratch (allocation-free requirement -> device globals)
__device__ float g_qkv[(size_t)T_TOK * QKV_W];     // 50.3 MB
__device__ float g_attn[(size_t)T_TOK * OUT_W];    // 33.6 MB
__device__ float g_invfreq_pi[HD/2];

// ---------------------------------------------------------------------------
// inv_freq table (divided by pi -> cospif/sinpif, immune to fast-math remap)
// ---------------------------------------------------------------------------
__global__ void init_invfreq_kernel() {
    int i = threadIdx.x;  // 0..63
    double inv = pow(1.0e6, -((double)(2 * i)) / 128.0);
    g_invfreq_pi[i] = (float)(inv / 3.14159265358979323846);
}

// ---------------------------------------------------------------------------
// GPT-J interleaved RoPE in-place on q heads (0..31) and k heads (32..39)
// ---------------------------------------------------------------------------
__global__ void rope_kernel(const int* __restrict__ positions,
                            float* __restrict__ qkv) {
    int t = blockIdx.x;
    int h = blockIdx.y;        // 0..39
    int i = threadIdx.x;       // 0..63
    float pos = (float)positions[t];
    float f = pos * g_invfreq_pi[i];
    float c = cospif(f);
    float s = sinpif(f);
    float* base = qkv + (size_t)t * QKV_W + h * HD;
    float x1 = base[2 * i];
    float x2 = base[2 * i + 1];
    base[2 * i]     = x1 * c - x2 * s;
    base[2 * i + 1] = x2 * c + x1 * s;
}

// ---------------------------------------------------------------------------
// common mma / ldmatrix helpers
// ---------------------------------------------------------------------------
__device__ __forceinline__ void mma16(float c[4], unsigned a0, unsigned a1,
                                      unsigned a2, unsigned a3,
                                      unsigned b0, unsigned b1) {
    asm volatile(
        "mma.sync.aligned.m16n8k16.row.col.f32.f16.f16.f32 "
        "{%0,%1,%2,%3}, {%4,%5,%6,%7}, {%8,%9}, {%0,%1,%2,%3};\n"
        : "+f"(c[0]), "+f"(c[1]), "+f"(c[2]), "+f"(c[3])
        : "r"(a0), "r"(a1), "r"(a2), "r"(a3), "r"(b0), "r"(b1));
}

__device__ __forceinline__ unsigned smem_u32(const void* p) {
    return (unsigned)__cvta_generic_to_shared(p);
}

__device__ __forceinline__ void ldsm_x4(unsigned& r0, unsigned& r1,
                                        unsigned& r2, unsigned& r3,
                                        unsigned addr) {
    asm volatile("ldmatrix.sync.aligned.m8n8.x4.shared.b16 {%0,%1,%2,%3}, [%4];\n"
                 : "=r"(r0), "=r"(r1), "=r"(r2), "=r"(r3) : "r"(addr));
}

__device__ __forceinline__ void ldsm_x4_t(unsigned& r0, unsigned& r1,
                                          unsigned& r2, unsigned& r3,
                                          unsigned addr) {
    asm volatile("ldmatrix.sync.aligned.m8n8.x4.trans.shared.b16 {%0,%1,%2,%3}, [%4];\n"
                 : "=r"(r0), "=r"(r1), "=r"(r2), "=r"(r3) : "r"(addr));
}

__device__ __forceinline__ unsigned packh2(float x, float y) {
    __half2 h = __floats2half2_rn(x, y);
    return *(unsigned*)&h;
}

// ---------------------------------------------------------------------------
// fp16 tensor-core GEMM: C[M,N] = A[M,K] @ B[K,N], row-major fp32 in/out,
// fp16 compute (same 10-bit mantissa as tf32, 2x throughput).
// 128x128 block tile, BK=32, 256 threads (8 warps, 2x4 -> 64x32 per warp),
// ldmatrix fragment loads, register-prefetch double buffering.
// M,N multiples of 128, K multiple of 32.
// ---------------------------------------------------------------------------
#define GA_STR 40    // halves per A smem row (32+8): conflict-free ldmatrix
#define GB_STR 136   // halves per B smem row (128+8): conflict-free ldmatrix

__global__ __launch_bounds__(256) void hgemm(const float* __restrict__ A,
                                             const float* __restrict__ B,
                                             float* __restrict__ C,
                                             int M, int N, int K) {
    __shared__ __half As[2][128 * GA_STR];   // 2 x 10240 B
    __shared__ __half Bs[2][32 * GB_STR];    // 2 x 8704 B

    int tid = threadIdx.x;
    int warp = tid >> 5;
    int lane = tid & 31;
    int wm = warp >> 2;            // 0..1
    int wn = warp & 3;             // 0..3
    int m_warp = wm * 64;
    int n_warp = wn * 32;
    int gid = lane >> 2;
    int tig = lane & 3;

    const float* Ab = A + (size_t)blockIdx.y * 128 * K;
    const float* Bb = B + (size_t)blockIdx.x * 128;
    float* Cb = C + (size_t)blockIdx.y * 128 * N + (size_t)blockIdx.x * 128;

    // ldmatrix lane addressing (shared by A and B-trans)
    int lrow = (lane & 7) + ((lane >> 3) & 1) * 8;   // row within 16
    int lcol8 = (lane >> 4) * 8;                     // 0 or 8

    float acc[4][4][4];
#pragma unroll
    for (int mt = 0; mt < 4; mt++)
#pragma unroll
        for (int ng = 0; ng < 4; ng++)
#pragma unroll
            for (int q = 0; q < 4; q++) acc[mt][ng][q] = 0.f;

    // ---- stage k0 = 0 into buffer 0 ----
#pragma unroll
    for (int it = 0; it < 4; it++) {
        int linear = tid + it * 256;
        int r = linear >> 3;              // 0..127
        int c4 = (linear & 7) * 4;        // 0..28
        float4 v = *(const float4*)(Ab + (size_t)r * K + c4);
        *(uint2*)(&As[0][r * GA_STR + c4]) =
            make_uint2(packh2(v.x, v.y), packh2(v.z, v.w));
    }
#pragma unroll
    for (int it = 0; it < 4; it++) {
        int linear = tid + it * 256;
        int r = linear >> 5;              // 0..31
        int c4 = (linear & 31) * 4;       // 0..124
        float4 v = *(const float4*)(Bb + (size_t)r * N + c4);
        *(uint2*)(&Bs[0][r * GB_STR + c4]) =
            make_uint2(packh2(v.x, v.y), packh2(v.z, v.w));
    }
    __syncthreads();

    int cur = 0;
    for (int k0 = 0; k0 < K; k0 += 32) {
        bool has_next = (k0 + 32) < K;
        float4 pa[4], pb[4];
        if (has_next) {
#pragma unroll
            for (int it = 0; it < 4; it++) {
                int linear = tid + it * 256;
                int r = linear >> 3;
                int c4 = (linear & 7) * 4;
                pa[it] = *(const float4*)(Ab + (size_t)r * K + (k0 + 32) + c4);
            }
#pragma unroll
            for (int it = 0; it < 4; it++) {
                int linear = tid + it * 256;
                int r = linear >> 5;
                int c4 = (linear & 31) * 4;
                pb[it] = *(const float4*)(Bb + (size_t)(k0 + 32 + r) * N + c4);
            }
        }

        const __half* Ac = As[cur];
        const __half* Bc = Bs[cur];
#pragma unroll
        for (int ks = 0; ks < 32; ks += 16) {
            unsigned bf[2][4];
#pragma unroll
            for (int nt = 0; nt < 2; nt++) {
                int rk = ks + lrow;
                int cn = n_warp + nt * 16 + lcol8;
                ldsm_x4_t(bf[nt][0], bf[nt][1], bf[nt][2], bf[nt][3],
                          smem_u32(Bc + rk * GB_STR + cn));
            }
#pragma unroll
            for (int mt = 0; mt < 4; mt++) {
                int ra = m_warp + mt * 16 + lrow;
                int ca = ks + lcol8;
                unsigned a0, a1, a2, a3;
                ldsm_x4(a0, a1, a2, a3, smem_u32(Ac + ra * GA_STR + ca));
                mma16(acc[mt][0], a0, a1, a2, a3, bf[0][0], bf[0][1]);
                mma16(acc[mt][1], a0, a1, a2, a3, bf[0][2], bf[0][3]);
                mma16(acc[mt][2], a0, a1, a2, a3, bf[1][0], bf[1][1]);
                mma16(acc[mt][3], a0, a1, a2, a3, bf[1][2], bf[1][3]);
            }
        }

        if (has_next) {
            int nxt = cur ^ 1;
#pragma unroll
            for (int it = 0; it < 4; it++) {
                int linear = tid + it * 256;
                int r = linear >> 3;
                int c4 = (linear & 7) * 4;
                *(uint2*)(&As[nxt][r * GA_STR + c4]) =
                    make_uint2(packh2(pa[it].x, pa[it].y), packh2(pa[it].z, pa[it].w));
            }
#pragma unroll
            for (int it = 0; it < 4; it++) {
                int linear = tid + it * 256;
                int r = linear >> 5;
                int c4 = (linear & 31) * 4;
                *(uint2*)(&Bs[nxt][r * GB_STR + c4]) =
                    make_uint2(packh2(pb[it].x, pb[it].y), packh2(pb[it].z, pb[it].w));
            }
            __syncthreads();
            cur = nxt;
        }
    }

    // epilogue
#pragma unroll
    for (int mt = 0; mt < 4; mt++) {
#pragma unroll
        for (int ng = 0; ng < 4; ng++) {
            int row0 = m_warp + mt * 16 + gid;
            int col  = n_warp + ng * 8 + tig * 2;
            *(float2*)(Cb + (size_t)row0 * N + col) =
                make_float2(acc[mt][ng][0], acc[mt][ng][1]);
            *(float2*)(Cb + (size_t)(row0 + 8) * N + col) =
                make_float2(acc[mt][ng][2], acc[mt][ng][3]);
        }
    }
}

// ---------------------------------------------------------------------------
// Flash attention: fp16 tensor cores with 3x hi/lo split (fp32-accurate).
// (unchanged from round 3)
// ---------------------------------------------------------------------------
#define QK_STR 68
#define VT_STR 36
#define PH_STR 36
#define VS_STR 132

#define QH0_OFF 0
#define QH1_OFF (128*QK_STR)
#define KH0_OFF (QH1_OFF + 128*QK_STR)
#define KH1_OFF (KH0_OFF + 64*QK_STR)
#define VT0_OFF (KH1_OFF + 64*QK_STR)
#define VT1_OFF (VT0_OFF + 128*VT_STR)
#define PH0_OFF (VT1_OFF + 128*VT_STR)
#define PH1_OFF (PH0_OFF + 128*PH_STR)
#define FLASH16_SMEM_WORDS (PH1_OFF + 128*PH_STR)
#define FLASH16_SMEM_BYTES (FLASH16_SMEM_WORDS * 4)

__device__ __forceinline__ void split2(float x, float y, unsigned& hi, unsigned& lo) {
    __half hx = __float2half_rn(x);
    __half hy = __float2half_rn(y);
    float rx = x - __half2float(hx);
    float ry = y - __half2float(hy);
    hi = (unsigned)__half_as_ushort(hx) | ((unsigned)__half_as_ushort(hy) << 16);
    lo = (unsigned)__half_as_ushort(__float2half_rn(rx)) |
         ((unsigned)__half_as_ushort(__float2half_rn(ry)) << 16);
}

__global__ __launch_bounds__(256) void flash16_kernel(const float* __restrict__ qkv,
                                                      float* __restrict__ out) {
    extern __shared__ unsigned sw[];
    unsigned* QH0 = sw + QH0_OFF;
    unsigned* QH1 = sw + QH1_OFF;
    unsigned* KH0 = sw + KH0_OFF;
    unsigned* KH1 = sw + KH1_OFF;
    unsigned* VT0 = sw + VT0_OFF;
    unsigned* VT1 = sw + VT1_OFF;
    unsigned* PH0 = sw + PH0_OFF;
    unsigned* PH1 = sw + PH1_OFF;
    float* Vst = (float*)(sw + PH0_OFF);

    int qb = gridDim.x - 1 - blockIdx.x;
    int hq = blockIdx.y;
    int hk = hq >> 2;
    int tid = threadIdx.x;
    int warp = tid >> 5;
    int lane = tid & 31;
    int gid = lane >> 2;
    int tig = lane & 3;
    int m0 = warp * 16;

    const float* qbase = qkv + (size_t)qb * 128 * QKV_W + hq * HD;
#pragma unroll
    for (int it = 0; it < 16; it++) {
        int idx = tid + it * 256;
        int r = idx >> 5;
        int c4 = (idx & 31) * 4;
        float4 q = *(const float4*)(qbase + (size_t)r * QKV_W + c4);
        q.x *= SM_SCALE; q.y *= SM_SCALE; q.z *= SM_SCALE; q.w *= SM_SCALE;
        unsigned h0, l0, h1, l1;
        split2(q.x, q.y, h0, l0);
        split2(q.z, q.w, h1, l1);
        int dw = c4 >> 1;
        QH0[r * QK_STR + dw]     = h0;
        QH0[r * QK_STR + dw + 1] = h1;
        QH1[r * QK_STR + dw]     = l0;
        QH1[r * QK_STR + dw + 1] = l1;
    }

    float mprev0 = -1e30f, mprev1 = -1e30f;
    float lsum0 = 0.f, lsum1 = 0.f;
    float acco[16][4];
#pragma unroll
    for (int dt = 0; dt < 16; dt++)
#pragma unroll
        for (int q = 0; q < 4; q++) acco[dt][q] = 0.f;

    int grow0 = qb * 128 + m0 + gid;
    int grow1 = grow0 + 8;

    int nkt = 2 * qb + 2;
    for (int kt = 0; kt < nkt; kt++) {
        __syncthreads();

        const float* kbase = qkv + (size_t)kt * 64 * QKV_W + NH * HD + hk * HD;
        const float* vbase = kbase + NKV * HD;
#pragma unroll
        for (int it = 0; it < 8; it++) {
            int idx = tid + it * 256;
            int r = idx >> 5;
            int c4 = (idx & 31) * 4;
            float4 k = *(const float4*)(kbase + (size_t)r * QKV_W + c4);
            unsigned h0, l0, h1, l1;
            split2(k.x, k.y, h0, l0);
            split2(k.z, k.w, h1, l1);
            int dw = c4 >> 1;
            KH0[r * QK_STR + dw]     = h0;
            KH0[r * QK_STR + dw + 1] = h1;
            KH1[r * QK_STR + dw]     = l0;
            KH1[r * QK_STR + dw + 1] = l1;
            float4 v = *(const float4*)(vbase + (size_t)r * QKV_W + c4);
            *(float4*)(Vst + r * VS_STR + c4) = v;
        }
        __syncthreads();

#pragma unroll
        for (int it = 0; it < 16; it++) {
            int linear = tid + it * 256;
            int jw = linear >> 7;
            int d = linear & 127;
            float v0 = Vst[(2 * jw) * VS_STR + d];
            float v1 = Vst[(2 * jw + 1) * VS_STR + d];
            unsigned hi, lo;
            split2(v0, v1, hi, lo);
            VT0[d * VT_STR + jw] = hi;
            VT1[d * VT_STR + jw] = lo;
        }
        __syncthreads();

        float accs[8][4];
#pragma unroll
        for (int nt = 0; nt < 8; nt++)
#pragma unroll
            for (int q = 0; q < 4; q++) accs[nt][q] = 0.f;

#pragma unroll
        for (int ks = 0; ks < 8; ks++) {
            int abase = (m0 + gid) * QK_STR + ks * 8 + tig;
            unsigned a00 = QH0[abase];
            unsigned a01 = QH0[abase + 8 * QK_STR];
            unsigned a02 = QH0[abase + 4];
            unsigned a03 = QH0[abase + 8 * QK_STR + 4];
            unsigned a10 = QH1[abase];
            unsigned a11 = QH1[abase + 8 * QK_STR];
            unsigned a12 = QH1[abase + 4];
            unsigned a13 = QH1[abase + 8 * QK_STR + 4];
#pragma unroll
            for (int nt = 0; nt < 8; nt++) {
                int bb = (nt * 8 + gid) * QK_STR + ks * 8 + tig;
                unsigned b00 = KH0[bb];
                unsigned b01 = KH0[bb + 4];
                unsigned b10 = KH1[bb];
                unsigned b11 = KH1[bb + 4];
                mma16(accs[nt], a00, a01, a02, a03, b00, b01);
                mma16(accs[nt], a00, a01, a02, a03, b10, b11);
                mma16(accs[nt], a10, a11, a12, a13, b00, b01);
            }
        }

        int colb = kt * 64 + 2 * tig;
        float mx0 = -1e30f, mx1 = -1e30f;
#pragma unroll
        for (int nt = 0; nt < 8; nt++) {
            int c0 = colb + nt * 8;
            int c1 = c0 + 1;
            accs[nt][0] = (c0 <= grow0) ? accs[nt][0] : -1e30f;
            accs[nt][1] = (c1 <= grow0) ? accs[nt][1] : -1e30f;
            accs[nt][2] = (c0 <= grow1) ? accs[nt][2] : -1e30f;
            accs[nt][3] = (c1 <= grow1) ? accs[nt][3] : -1e30f;
            mx0 = fmaxf(mx0, fmaxf(accs[nt][0], accs[nt][1]));
            mx1 = fmaxf(mx1, fmaxf(accs[nt][2], accs[nt][3]));
        }
        mx0 = fmaxf(mx0, __shfl_xor_sync(0xffffffffu, mx0, 1));
        mx0 = fmaxf(mx0, __shfl_xor_sync(0xffffffffu, mx0, 2));
        mx1 = fmaxf(mx1, __shfl_xor_sync(0xffffffffu, mx1, 1));
        mx1 = fmaxf(mx1, __shfl_xor_sync(0xffffffffu, mx1, 2));

        float mn0 = fmaxf(mprev0, mx0);
        float mn1 = fmaxf(mprev1, mx1);
        float corr0 = __expf(mprev0 - mn0);
        float corr1 = __expf(mprev1 - mn1);
        mprev0 = mn0;
        mprev1 = mn1;

        float sum0 = 0.f, sum1 = 0.f;
#pragma unroll
        for (int nt = 0; nt < 8; nt++) {
            accs[nt][0] = __expf(accs[nt][0] - mn0);
            accs[nt][1] = __expf(accs[nt][1] - mn0);
            accs[nt][2] = __expf(accs[nt][2] - mn1);
            accs[nt][3] = __expf(accs[nt][3] - mn1);
            sum0 += accs[nt][0] + accs[nt][1];
            sum1 += accs[nt][2] + accs[nt][3];
        }
        sum0 += __shfl_xor_sync(0xffffffffu, sum0, 1);
        sum0 += __shfl_xor_sync(0xffffffffu, sum0, 2);
        sum1 += __shfl_xor_sync(0xffffffffu, sum1, 1);
        sum1 += __shfl_xor_sync(0xffffffffu, sum1, 2);
        lsum0 = lsum0 * corr0 + sum0;
        lsum1 = lsum1 * corr1 + sum1;

#pragma unroll
        for (int dt = 0; dt < 16; dt++) {
            acco[dt][0] *= corr0;
            acco[dt][1] *= corr0;
            acco[dt][2] *= corr1;
            acco[dt][3] *= corr1;
        }

#pragma unroll
        for (int nt = 0; nt < 8; nt++) {
            unsigned hi0, lo0, hi1, lo1;
            split2(accs[nt][0], accs[nt][1], hi0, lo0);
            split2(accs[nt][2], accs[nt][3], hi1, lo1);
            int w0 = (m0 + gid) * PH_STR + nt * 4 + tig;
            int w1 = (m0 + gid + 8) * PH_STR + nt * 4 + tig;
            PH0[w0] = hi0;
            PH1[w0] = lo0;
            PH0[w1] = hi1;
            PH1[w1] = lo1;
        }
        __syncwarp();

#pragma unroll
        for (int ks = 0; ks < 4; ks++) {
            int abase = (m0 + gid) * PH_STR + ks * 8 + tig;
            unsigned a00 = PH0[abase];
            unsigned a01 = PH0[abase + 8 * PH_STR];
            unsigned a02 = PH0[abase + 4];
            unsigned a03 = PH0[abase + 8 * PH_STR + 4];
            unsigned a10 = PH1[abase];
            unsigned a11 = PH1[abase + 8 * PH_STR];
            unsigned a12 = PH1[abase + 4];
            unsigned a13 = PH1[abase + 8 * PH_STR + 4];
#pragma unroll
            for (int dt = 0; dt < 16; dt++) {
                int vb = (dt * 8 + gid) * VT_STR + ks * 8 + tig;
                unsigned b00 = VT0[vb];
                unsigned b01 = VT0[vb + 4];
                unsigned b10 = VT1[vb];
                unsigned b11 = VT1[vb + 4];
                mma16(acco[dt], a00, a01, a02, a03, b00, b01);
                mma16(acco[dt], a00, a01, a02, a03, b10, b11);
                mma16(acco[dt], a10, a11, a12, a13, b00, b01);
            }
        }
    }

    float il0 = 1.0f / lsum0;
    float il1 = 1.0f / lsum1;
    float* o0 = out + (size_t)grow0 * OUT_W + hq * HD;
    float* o1 = out + (size_t)grow1 * OUT_W + hq * HD;
#pragma unroll
    for (int dt = 0; dt < 16; dt++) {
        int col = dt * 8 + 2 * tig;
        *(float2*)(o0 + col) = make_float2(acco[dt][0] * il0, acco[dt][1] * il0);
        *(float2*)(o1 + col) = make_float2(acco[dt][2] * il1, acco[dt][3] * il1);
    }
}

// ---------------------------------------------------------------------------
// launch
// ---------------------------------------------------------------------------
extern "C" void kernel_launch(void* const* d_in, const int* in_sizes, int n_in,
                              void* d_out, int out_size) {
    (void)in_sizes; (void)n_in; (void)out_size;
    const int*   positions = (const int*)d_in[0];
    const float* hidden    = (const float*)d_in[1];
    const float* Wqkv      = (const float*)d_in[2];
    const float* Wo        = (const float*)d_in[3];
    float*       out       = (float*)d_out;

    void* qkv_p  = nullptr;
    void* attn_p = nullptr;
    cudaGetSymbolAddress(&qkv_p, g_qkv);
    cudaGetSymbolAddress(&attn_p, g_attn);
    float* qkv  = (float*)qkv_p;
    float* attn = (float*)attn_p;

    cudaFuncSetAttribute(flash16_kernel,
                         cudaFuncAttributeMaxDynamicSharedMemorySize,
                         FLASH16_SMEM_BYTES);

    init_invfreq_kernel<<<1, 64>>>();

    // qkv = hidden @ Wqkv  (fp16 tensor cores)
    hgemm<<<dim3(QKV_W / 128, T_TOK / 128), 256>>>(hidden, Wqkv, qkv,
                                                   T_TOK, QKV_W, HID);
    // RoPE on q + k heads
    rope_kernel<<<dim3(T_TOK, NH + NKV), 64>>>(positions, qkv);

    // flash attention (fp16 3x tensor cores)
    flash16_kernel<<<dim3(T_TOK / 128, NH), 256, FLASH16_SMEM_BYTES>>>(qkv, attn);

    // out = attn @ Wo  (fp16 tensor cores)
    hgemm<<<dim3(HID / 128, T_TOK / 128), 256>>>(attn, Wo, out,
                                                 T_TOK, HID, HID);
}

// round 5
// speedup vs baseline: 5.3800x; 1.2809x over previous
#include <cuda_runtime.h>
#include <cuda_fp16.h>
#include <cuda_bf16.h>
#include <math.h>

// Problem constants
#define T_TOK 2048
#define HID   4096
#define NH    32
#define NKV   8
#define HD    128
#define QKV_W ((NH + 2*NKV) * HD)   // 6144
#define OUT_W (NH * HD)             // 4096
#define SM_SCALE 0.08838834764831843f  // 1/sqrt(128)

// ---------------------------------------------------------------------------
// Scratch (allocation-free -> device globals), all 16B-aligned for cp.async
// ---------------------------------------------------------------------------
__device__ __align__(16) float    g_qkv[(size_t)T_TOK * QKV_W];        // 50.3 MB
__device__ __align__(16) unsigned g_Qh[(size_t)T_TOK * 2048];          // q hi plane (half2 words)
__device__ __align__(16) unsigned g_Ql[(size_t)T_TOK * 2048];          // q lo plane
__device__ __align__(16) unsigned g_Kh[(size_t)T_TOK * 512];
__device__ __align__(16) unsigned g_Kl[(size_t)T_TOK * 512];
__device__ __align__(16) unsigned g_VTh[(size_t)NKV * HD * (T_TOK/2)]; // V transposed hi
__device__ __align__(16) unsigned g_VTl[(size_t)NKV * HD * (T_TOK/2)];
__device__ __align__(16) __half   g_h16[(size_t)T_TOK * HID];
__device__ __align__(16) __half   g_wqkv16[(size_t)HID * QKV_W];
__device__ __align__(16) __half   g_wo16[(size_t)OUT_W * HID];
__device__ __align__(16) __half   g_attn16[(size_t)T_TOK * OUT_W];
__device__ float g_invfreq_pi[HD/2];

// ---------------------------------------------------------------------------
// helpers
// ---------------------------------------------------------------------------
__device__ __forceinline__ unsigned packh2(float x, float y) {
    __half2 h = __floats2half2_rn(x, y);
    return *(unsigned*)&h;
}

__device__ __forceinline__ void split2(float x, float y, unsigned& hi, unsigned& lo) {
    __half hx = __float2half_rn(x);
    __half hy = __float2half_rn(y);
    float rx = x - __half2float(hx);
    float ry = y - __half2float(hy);
    hi = (unsigned)__half_as_ushort(hx) | ((unsigned)__half_as_ushort(hy) << 16);
    lo = (unsigned)__half_as_ushort(__float2half_rn(rx)) |
         ((unsigned)__half_as_ushort(__float2half_rn(ry)) << 16);
}

__device__ __forceinline__ void mma16(float c[4], unsigned a0, unsigned a1,
                                      unsigned a2, unsigned a3,
                                      unsigned b0, unsigned b1) {
    asm volatile(
        "mma.sync.aligned.m16n8k16.row.col.f32.f16.f16.f32 "
        "{%0,%1,%2,%3}, {%4,%5,%6,%7}, {%8,%9}, {%0,%1,%2,%3};\n"
        : "+f"(c[0]), "+f"(c[1]), "+f"(c[2]), "+f"(c[3])
        : "r"(a0), "r"(a1), "r"(a2), "r"(a3), "r"(b0), "r"(b1));
}

__device__ __forceinline__ unsigned smem_u32(const void* p) {
    return (unsigned)__cvta_generic_to_shared(p);
}

__device__ __forceinline__ void ldsm_x4(unsigned& r0, unsigned& r1,
                                        unsigned& r2, unsigned& r3,
                                        unsigned addr) {
    asm volatile("ldmatrix.sync.aligned.m8n8.x4.shared.b16 {%0,%1,%2,%3}, [%4];\n"
                 : "=r"(r0), "=r"(r1), "=r"(r2), "=r"(r3) : "r"(addr));
}

__device__ __forceinline__ void ldsm_x4_t(unsigned& r0, unsigned& r1,
                                          unsigned& r2, unsigned& r3,
                                          unsigned addr) {
    asm volatile("ldmatrix.sync.aligned.m8n8.x4.trans.shared.b16 {%0,%1,%2,%3}, [%4];\n"
                 : "=r"(r0), "=r"(r1), "=r"(r2), "=r"(r3) : "r"(addr));
}

#define CP16(dst, src) \
    asm volatile("cp.async.ca.shared.global [%0], [%1], 16;\n" \
                 :: "r"(dst), "l"(src))
#define CPCOMMIT() asm volatile("cp.async.commit_group;\n")
#define CPWAIT0()  asm volatile("cp.async.wait_group 0;\n")

// ---------------------------------------------------------------------------
// small kernels
// ---------------------------------------------------------------------------
__global__ void init_invfreq_kernel() {
    int i = threadIdx.x;
    double inv = pow(1.0e6, -((double)(2 * i)) / 128.0);
    g_invfreq_pi[i] = (float)(inv / 3.14159265358979323846);
}

__global__ void conv_f16_kernel(const float4* __restrict__ src,
                                uint2* __restrict__ dst, int n4) {
    int i = blockIdx.x * blockDim.x + threadIdx.x;
    if (i < n4) {
        float4 v = src[i];
        dst[i] = make_uint2(packh2(v.x, v.y), packh2(v.z, v.w));
    }
}

// RoPE + scale + hi/lo split for Q and K heads -> global half2 planes
__global__ void prep_qk_kernel(const int* __restrict__ positions,
                               const float* __restrict__ qkv) {
    int t = blockIdx.x;
    int h = blockIdx.y;        // 0..39
    int i = threadIdx.x;       // 0..63
    float pos = (float)positions[t];
    float f = pos * g_invfreq_pi[i];
    float c = cospif(f);
    float s = sinpif(f);
    const float* base = qkv + (size_t)t * QKV_W + h * HD;
    float x1 = base[2 * i];
    float x2 = base[2 * i + 1];
    float o1 = x1 * c - x2 * s;
    float o2 = x2 * c + x1 * s;
    unsigned hi, lo;
    if (h < NH) {
        o1 *= SM_SCALE;
        o2 *= SM_SCALE;
        split2(o1, o2, hi, lo);
        g_Qh[(size_t)t * 2048 + h * 64 + i] = hi;
        g_Ql[(size_t)t * 2048 + h * 64 + i] = lo;
    } else {
        int kh = h - NH;
        split2(o1, o2, hi, lo);
        g_Kh[(size_t)t * 512 + kh * 64 + i] = hi;
        g_Kl[(size_t)t * 512 + kh * 64 + i] = lo;
    }
}

// V split + transpose: VT[hk][d][token-pair word]
__global__ __launch_bounds__(256) void prep_v_kernel(const float* __restrict__ qkv) {
    __shared__ float Vs[64 * 133];
    int bt = blockIdx.x;     // token tile /64
    int hk = blockIdx.y;     // 0..7
    int tid = threadIdx.x;
    const float* vb = qkv + (size_t)bt * 64 * QKV_W + (NH + NKV) * HD + hk * HD;
#pragma unroll
    for (int it = 0; it < 8; it++) {
        int idx = tid + it * 256;
        int r = idx >> 5;
        int c4 = (idx & 31) * 4;
        float4 v = *(const float4*)(vb + (size_t)r * QKV_W + c4);
        Vs[r * 133 + c4 + 0] = v.x;
        Vs[r * 133 + c4 + 1] = v.y;
        Vs[r * 133 + c4 + 2] = v.z;
        Vs[r * 133 + c4 + 3] = v.w;
    }
    __syncthreads();
#pragma unroll
    for (int it = 0; it < 16; it++) {
        int d = it * 8 + (tid >> 5);    // 0..127
        int jw = tid & 31;              // token pair within tile
        float v0 = Vs[(2 * jw) * 133 + d];
        float v1 = Vs[(2 * jw + 1) * 133 + d];
        unsigned hi, lo;
        split2(v0, v1, hi, lo);
        size_t w = (size_t)(hk * 128 + d) * (T_TOK / 2) + bt * 32 + jw;
        g_VTh[w] = hi;
        g_VTl[w] = lo;
    }
}

// ---------------------------------------------------------------------------
// fp16 HGEMM with cp.async double buffering.
// C[M,N] fp32 = A[M,K] @ B[K,N], A/B half row-major.
// 128x128 tile, BK=32, 8 warps (2x4 -> 64x32 per warp).
// ---------------------------------------------------------------------------
#define GA_STR 40
#define GB_STR 136

__global__ __launch_bounds__(256) void hgemm(const __half* __restrict__ A,
                                             const __half* __restrict__ B,
                                             float* __restrict__ C,
                                             int M, int N, int K) {
    __shared__ __half As[2][128 * GA_STR];
    __shared__ __half Bs[2][32 * GB_STR];

    int tid = threadIdx.x;
    int warp = tid >> 5;
    int lane = tid & 31;
    int wm = warp >> 2;
    int wn = warp & 3;
    int m_warp = wm * 64;
    int n_warp = wn * 32;
    int gid = lane >> 2;
    int tig = lane & 3;
    int lrow = (lane & 7) + ((lane >> 3) & 1) * 8;
    int lcol8 = (lane >> 4) * 8;

    const __half* Ab = A + (size_t)blockIdx.y * 128 * K;
    const __half* Bb = B + (size_t)blockIdx.x * 128;
    float* Cb = C + (size_t)blockIdx.y * 128 * N + (size_t)blockIdx.x * 128;

    float acc[4][4][4];
#pragma unroll
    for (int mt = 0; mt < 4; mt++)
#pragma unroll
        for (int ng = 0; ng < 4; ng++)
#pragma unroll
            for (int q = 0; q < 4; q++) acc[mt][ng][q] = 0.f;

    // stage(buf, k0)
    auto stage = [&](int buf, int k0) {
#pragma unroll
        for (int it = 0; it < 2; it++) {
            int idx = tid + it * 256;          // 0..511
            int r = idx >> 2;                  // 0..127
            int c8 = (idx & 3) * 8;            // 0..24
            CP16(smem_u32(&As[buf][r * GA_STR + c8]),
                 Ab + (size_t)r * K + k0 + c8);
        }
#pragma unroll
        for (int it = 0; it < 2; it++) {
            int idx = tid + it * 256;
            int r = idx >> 4;                  // 0..31
            int c8 = (idx & 15) * 8;           // 0..120
            CP16(smem_u32(&Bs[buf][r * GB_STR + c8]),
                 Bb + (size_t)(k0 + r) * N + c8);
        }
    };

    stage(0, 0);
    CPCOMMIT();

    int cur = 0;
    for (int k0 = 0; k0 < K; k0 += 32) {
        CPWAIT0();
        __syncthreads();
        if (k0 + 32 < K) {
            stage(cur ^ 1, k0 + 32);
            CPCOMMIT();
        }

        const __half* Ac = As[cur];
        const __half* Bc = Bs[cur];
#pragma unroll
        for (int ks = 0; ks < 32; ks += 16) {
            unsigned bf[2][4];
#pragma unroll
            for (int nt = 0; nt < 2; nt++) {
                ldsm_x4_t(bf[nt][0], bf[nt][1], bf[nt][2], bf[nt][3],
                          smem_u32(Bc + (ks + lrow) * GB_STR + n_warp + nt * 16 + lcol8));
            }
#pragma unroll
            for (int mt = 0; mt < 4; mt++) {
                unsigned a0, a1, a2, a3;
                ldsm_x4(a0, a1, a2, a3,
                        smem_u32(Ac + (m_warp + mt * 16 + lrow) * GA_STR + ks + lcol8));
                mma16(acc[mt][0], a0, a1, a2, a3, bf[0][0], bf[0][1]);
                mma16(acc[mt][1], a0, a1, a2, a3, bf[0][2], bf[0][3]);
                mma16(acc[mt][2], a0, a1, a2, a3, bf[1][0], bf[1][1]);
                mma16(acc[mt][3], a0, a1, a2, a3, bf[1][2], bf[1][3]);
            }
        }
        cur ^= 1;
    }

#pragma unroll
    for (int mt = 0; mt < 4; mt++) {
#pragma unroll
        for (int ng = 0; ng < 4; ng++) {
            int row0 = m_warp + mt * 16 + gid;
            int col  = n_warp + ng * 8 + tig * 2;
            *(float2*)(Cb + (size_t)row0 * N + col) =
                make_float2(acc[mt][ng][0], acc[mt][ng][1]);
            *(float2*)(Cb + (size_t)(row0 + 8) * N + col) =
                make_float2(acc[mt][ng][2], acc[mt][ng][3]);
        }
    }
}

// ---------------------------------------------------------------------------
// Flash attention v3: precomputed split planes, cp.async staging, ldmatrix.
// BQ=128, BK=64, 256 threads (8 warps x 16 rows). Writes attn as fp16.
// ---------------------------------------------------------------------------
#define QK_STR 68
#define VT_STR 36
#define PH_STR 36

#define QH0_OFF 0
#define QH1_OFF (128*QK_STR)
#define KH0_OFF (QH1_OFF + 128*QK_STR)
#define KH1_OFF (KH0_OFF + 64*QK_STR)
#define VT0_OFF (KH1_OFF + 64*QK_STR)
#define VT1_OFF (VT0_OFF + 128*VT_STR)
#define PH0_OFF (VT1_OFF + 128*VT_STR)
#define PH1_OFF (PH0_OFF + 128*PH_STR)
#define FLASH_SMEM_WORDS (PH1_OFF + 128*PH_STR)
#define FLASH_SMEM_BYTES (FLASH_SMEM_WORDS * 4)   // 178176

__global__ __launch_bounds__(256) void flash16_kernel(__half* __restrict__ out16) {
    extern __shared__ unsigned sw[];
    unsigned* QH0 = sw + QH0_OFF;
    unsigned* QH1 = sw + QH1_OFF;
    unsigned* KH0 = sw + KH0_OFF;
    unsigned* KH1 = sw + KH1_OFF;
    unsigned* VT0 = sw + VT0_OFF;
    unsigned* VT1 = sw + VT1_OFF;
    unsigned* PH0 = sw + PH0_OFF;
    unsigned* PH1 = sw + PH1_OFF;

    int qb = gridDim.x - 1 - blockIdx.x;   // heavy blocks first
    int hq = blockIdx.y;
    int hk = hq >> 2;
    int tid = threadIdx.x;
    int warp = tid >> 5;
    int lane = tid & 31;
    int gid = lane >> 2;
    int tig = lane & 3;
    int m0 = warp * 16;

    // fragment lane addressing
    int lrow  = (lane & 7) + ((lane >> 3) & 1) * 8;   // A-frag
    int acol4 = ((lane >> 4) & 1) * 4;
    int krow  = (lane & 7) + ((lane >> 4) & 1) * 8;   // B-frag (non-trans x4 over 2 n-tiles)
    int kcol4 = ((lane >> 3) & 1) * 4;

    // ---- stage Q (cp.async, once) ----
#pragma unroll
    for (int it = 0; it < 8; it++) {
        int idx = tid + it * 256;          // 0..2047
        int r = idx >> 4;                  // 0..127
        int c = (idx & 15) * 4;            // 0..60
        const unsigned* s0 = g_Qh + (size_t)(qb * 128 + r) * 2048 + hq * 64 + c;
        const unsigned* s1 = g_Ql + (size_t)(qb * 128 + r) * 2048 + hq * 64 + c;
        CP16(smem_u32(QH0 + r * QK_STR + c), s0);
        CP16(smem_u32(QH1 + r * QK_STR + c), s1);
    }

    float mprev0 = -1e30f, mprev1 = -1e30f;
    float lsum0 = 0.f, lsum1 = 0.f;
    float acco[16][4];
#pragma unroll
    for (int dt = 0; dt < 16; dt++)
#pragma unroll
        for (int q = 0; q < 4; q++) acco[dt][q] = 0.f;

    int grow0 = qb * 128 + m0 + gid;
    int grow1 = grow0 + 8;

    int nkt = 2 * qb + 2;
    for (int kt = 0; kt < nkt; kt++) {
        __syncthreads();   // prior consumers of KH/VT done

        // ---- stage K + VT (cp.async) ----
#pragma unroll
        for (int it = 0; it < 4; it++) {
            int idx = tid + it * 256;      // 0..1023
            int r = idx >> 4;              // 0..63
            int c = (idx & 15) * 4;
            const unsigned* s0 = g_Kh + (size_t)(kt * 64 + r) * 512 + hk * 64 + c;
            const unsigned* s1 = g_Kl + (size_t)(kt * 64 + r) * 512 + hk * 64 + c;
            CP16(smem_u32(KH0 + r * QK_STR + c), s0);
            CP16(smem_u32(KH1 + r * QK_STR + c), s1);
        }
#pragma unroll
        for (int it = 0; it < 4; it++) {
            int idx = tid + it * 256;
            int r = idx >> 3;              // d: 0..127
            int c = (idx & 7) * 4;         // 0..28
            const unsigned* s0 = g_VTh + (size_t)(hk * 128 + r) * (T_TOK/2) + kt * 32 + c;
            const unsigned* s1 = g_VTl + (size_t)(hk * 128 + r) * (T_TOK/2) + kt * 32 + c;
            CP16(smem_u32(VT0 + r * VT_STR + c), s0);
            CP16(smem_u32(VT1 + r * VT_STR + c), s1);
        }
        CPCOMMIT();
        CPWAIT0();
        __syncthreads();

        // ---- S = Q K^T (3x fp16 split) via ldmatrix ----
        float accs[8][4];
#pragma unroll
        for (int nt = 0; nt < 8; nt++)
#pragma unroll
            for (int q = 0; q < 4; q++) accs[nt][q] = 0.f;

#pragma unroll
        for (int ks = 0; ks < 8; ks++) {
            unsigned ah[4], al[4];
            ldsm_x4(ah[0], ah[1], ah[2], ah[3],
                    smem_u32(QH0 + (m0 + lrow) * QK_STR + ks * 8 + acol4));
            ldsm_x4(al[0], al[1], al[2], al[3],
                    smem_u32(QH1 + (m0 + lrow) * QK_STR + ks * 8 + acol4));
#pragma unroll
            for (int nt2 = 0; nt2 < 4; nt2++) {
                unsigned bh[4], bl[4];
                ldsm_x4(bh[0], bh[1], bh[2], bh[3],
                        smem_u32(KH0 + (nt2 * 16 + krow) * QK_STR + ks * 8 + kcol4));
                ldsm_x4(bl[0], bl[1], bl[2], bl[3],
                        smem_u32(KH1 + (nt2 * 16 + krow) * QK_STR + ks * 8 + kcol4));
                mma16(accs[2*nt2],   ah[0], ah[1], ah[2], ah[3], bh[0], bh[1]);
                mma16(accs[2*nt2],   ah[0], ah[1], ah[2], ah[3], bl[0], bl[1]);
                mma16(accs[2*nt2],   al[0], al[1], al[2], al[3], bh[0], bh[1]);
                mma16(accs[2*nt2+1], ah[0], ah[1], ah[2], ah[3], bh[2], bh[3]);
                mma16(accs[2*nt2+1], ah[0], ah[1], ah[2], ah[3], bl[2], bl[3]);
                mma16(accs[2*nt2+1], al[0], al[1], al[2], al[3], bh[2], bh[3]);
            }
        }

        // ---- causal mask + online softmax ----
        int colb = kt * 64 + 2 * tig;
        float mx0 = -1e30f, mx1 = -1e30f;
#pragma unroll
        for (int nt = 0; nt < 8; nt++) {
            int c0 = colb + nt * 8;
            int c1 = c0 + 1;
            accs[nt][0] = (c0 <= grow0) ? accs[nt][0] : -1e30f;
            accs[nt][1] = (c1 <= grow0) ? accs[nt][1] : -1e30f;
            accs[nt][2] = (c0 <= grow1) ? accs[nt][2] : -1e30f;
            accs[nt][3] = (c1 <= grow1) ? accs[nt][3] : -1e30f;
            mx0 = fmaxf(mx0, fmaxf(accs[nt][0], accs[nt][1]));
            mx1 = fmaxf(mx1, fmaxf(accs[nt][2], accs[nt][3]));
        }
        mx0 = fmaxf(mx0, __shfl_xor_sync(0xffffffffu, mx0, 1));
        mx0 = fmaxf(mx0, __shfl_xor_sync(0xffffffffu, mx0, 2));
        mx1 = fmaxf(mx1, __shfl_xor_sync(0xffffffffu, mx1, 1));
        mx1 = fmaxf(mx1, __shfl_xor_sync(0xffffffffu, mx1, 2));

        float mn0 = fmaxf(mprev0, mx0);
        float mn1 = fmaxf(mprev1, mx1);
        float corr0 = __expf(mprev0 - mn0);
        float corr1 = __expf(mprev1 - mn1);
        mprev0 = mn0;
        mprev1 = mn1;

        float sum0 = 0.f, sum1 = 0.f;
#pragma unroll
        for (int nt = 0; nt < 8; nt++) {
            accs[nt][0] = __expf(accs[nt][0] - mn0);
            accs[nt][1] = __expf(accs[nt][1] - mn0);
            accs[nt][2] = __expf(accs[nt][2] - mn1);
            accs[nt][3] = __expf(accs[nt][3] - mn1);
            sum0 += accs[nt][0] + accs[nt][1];
            sum1 += accs[nt][2] + accs[nt][3];
        }
        sum0 += __shfl_xor_sync(0xffffffffu, sum0, 1);
        sum0 += __shfl_xor_sync(0xffffffffu, sum0, 2);
        sum1 += __shfl_xor_sync(0xffffffffu, sum1, 1);
        sum1 += __shfl_xor_sync(0xffffffffu, sum1, 2);
        lsum0 = lsum0 * corr0 + sum0;
        lsum1 = lsum1 * corr1 + sum1;

#pragma unroll
        for (int dt = 0; dt < 16; dt++) {
            acco[dt][0] *= corr0;
            acco[dt][1] *= corr0;
            acco[dt][2] *= corr1;
            acco[dt][3] *= corr1;
        }

        // ---- write P hi/lo (warp-private rows) ----
#pragma unroll
        for (int nt = 0; nt < 8; nt++) {
            unsigned hi0, lo0, hi1, lo1;
            split2(accs[nt][0], accs[nt][1], hi0, lo0);
            split2(accs[nt][2], accs[nt][3], hi1, lo1);
            int w0 = (m0 + gid) * PH_STR + nt * 4 + tig;
            int w1 = (m0 + gid + 8) * PH_STR + nt * 4 + tig;
            PH0[w0] = hi0;
            PH1[w0] = lo0;
            PH0[w1] = hi1;
            PH1[w1] = lo1;
        }
        __syncwarp();

        // ---- O += P V (3x fp16 split) via ldmatrix ----
#pragma unroll
        for (int ks = 0; ks < 4; ks++) {
            unsigned ah[4], al[4];
            ldsm_x4(ah[0], ah[1], ah[2], ah[3],
                    smem_u32(PH0 + (m0 + lrow) * PH_STR + ks * 8 + acol4));
            ldsm_x4(al[0], al[1], al[2], al[3],
                    smem_u32(PH1 + (m0 + lrow) * PH_STR + ks * 8 + acol4));
#pragma unroll
            for (int dt2 = 0; dt2 < 8; dt2++) {
                unsigned vh[4], vl[4];
                ldsm_x4(vh[0], vh[1], vh[2], vh[3],
                        smem_u32(VT0 + (dt2 * 16 + krow) * VT_STR + ks * 8 + kcol4));
                ldsm_x4(vl[0], vl[1], vl[2], vl[3],
                        smem_u32(VT1 + (dt2 * 16 + krow) * VT_STR + ks * 8 + kcol4));
                mma16(acco[2*dt2],   ah[0], ah[1], ah[2], ah[3], vh[0], vh[1]);
                mma16(acco[2*dt2],   ah[0], ah[1], ah[2], ah[3], vl[0], vl[1]);
                mma16(acco[2*dt2],   al[0], al[1], al[2], al[3], vh[0], vh[1]);
                mma16(acco[2*dt2+1], ah[0], ah[1], ah[2], ah[3], vh[2], vh[3]);
                mma16(acco[2*dt2+1], ah[0], ah[1], ah[2], ah[3], vl[2], vl[3]);
                mma16(acco[2*dt2+1], al[0], al[1], al[2], al[3], vh[2], vh[3]);
            }
        }
    }

    // ---- epilogue: write attn as fp16 ----
    float il0 = 1.0f / lsum0;
    float il1 = 1.0f / lsum1;
    __half* o0 = out16 + (size_t)grow0 * OUT_W + hq * HD;
    __half* o1 = out16 + (size_t)grow1 * OUT_W + hq * HD;
#pragma unroll
    for (int dt = 0; dt < 16; dt++) {
        int col = dt * 8 + 2 * tig;
        *(unsigned*)(o0 + col) = packh2(acco[dt][0] * il0, acco[dt][1] * il0);
        *(unsigned*)(o1 + col) = packh2(acco[dt][2] * il1, acco[dt][3] * il1);
    }
}

// ---------------------------------------------------------------------------
// launch
// ---------------------------------------------------------------------------
extern "C" void kernel_launch(void* const* d_in, const int* in_sizes, int n_in,
                              void* d_out, int out_size) {
    (void)in_sizes; (void)n_in; (void)out_size;
    const int*   positions = (const int*)d_in[0];
    const float* hidden    = (const float*)d_in[1];
    const float* Wqkv      = (const float*)d_in[2];
    const float* Wo        = (const float*)d_in[3];
    float*       out       = (float*)d_out;

    void *qkv_p, *h16_p, *wqkv16_p, *wo16_p, *attn16_p;
    cudaGetSymbolAddress(&qkv_p, g_qkv);
    cudaGetSymbolAddress(&h16_p, g_h16);
    cudaGetSymbolAddress(&wqkv16_p, g_wqkv16);
    cudaGetSymbolAddress(&wo16_p, g_wo16);
    cudaGetSymbolAddress(&attn16_p, g_attn16);
    float*  qkv    = (float*)qkv_p;
    __half* h16    = (__half*)h16_p;
    __half* wqkv16 = (__half*)wqkv16_p;
    __half* wo16   = (__half*)wo16_p;
    __half* attn16 = (__half*)attn16_p;

    cudaFuncSetAttribute(flash16_kernel,
                         cudaFuncAttributeMaxDynamicSharedMemorySize,
                         FLASH_SMEM_BYTES);

    init_invfreq_kernel<<<1, 64>>>();

    // fp32 -> fp16 conversions (weights + activations)
    {
        int n4 = T_TOK * HID / 4;
        conv_f16_kernel<<<(n4 + 255) / 256, 256>>>((const float4*)hidden,
                                                   (uint2*)h16, n4);
        n4 = HID * QKV_W / 4;
        conv_f16_kernel<<<(n4 + 255) / 256, 256>>>((const float4*)Wqkv,
                                                   (uint2*)wqkv16, n4);
        n4 = OUT_W * HID / 4;
        conv_f16_kernel<<<(n4 + 255) / 256, 256>>>((const float4*)Wo,
                                                   (uint2*)wo16, n4);
    }

    // qkv = hidden @ Wqkv (fp16 tensor cores, fp32 out)
    hgemm<<<dim3(QKV_W / 128, T_TOK / 128), 256>>>(h16, wqkv16, qkv,
                                                   T_TOK, QKV_W, HID);

    // RoPE + split planes; V split + transpose
    prep_qk_kernel<<<dim3(T_TOK, NH + NKV), 64>>>(positions, qkv);
    prep_v_kernel<<<dim3(T_TOK / 64, NKV), 256>>>(qkv);

    // flash attention
    flash16_kernel<<<dim3(T_TOK / 128, NH), 256, FLASH_SMEM_BYTES>>>(attn16);

    // out = attn @ Wo
    hgemm<<<dim3(HID / 128, T_TOK / 128), 256>>>(attn16, wo16, out,
                                                 T_TOK, HID, HID);
}